// round 14
// baseline (speedup 1.0000x reference)
#include <cuda_runtime.h>
#include <cuda_fp16.h>
#include <math.h>

#define C_    256
#define NLAT_ 256
#define NLON_ 512
#define L_    256
#define M_    257
#define NREF_ 64
#define S_    (NLAT_*NLON_)
#define K2C_  512
#define MP_   544               // 2*M=514 padded to mult of 32

#define XS_SZ   ((size_t)C_*S_)
#define LW_SZ   ((size_t)L_*M_*NLAT_)
#define LGT_SZ  ((size_t)M_*NLAT_*L_)
#define WC_SZ   ((size_t)L_*C_*K2C_)
#define F_SZ    ((size_t)2*M_*C_*NLAT_)
#define H_SZ    ((size_t)L_*M_*K2C_)
#define XSP_SZ  ((size_t)M_*C_*L_)
#define G2_SZ   ((size_t)NLAT_*C_*MP_)
#define DCS_SZ  ((size_t)2*M_*NLON_)
#define D2_SZ   ((size_t)NLON_*MP_)

__device__ __align__(128) __half g_x_h[XS_SZ];
__device__ __align__(128) __half g_xt_h[XS_SZ];
__device__ __align__(128) __half g_lw_h[LW_SZ];
__device__ __align__(128) __half g_lg_h[LGT_SZ];
__device__ __align__(128) __half g_wr_h[WC_SZ];
__device__ __align__(128) __half g_wi_h[WC_SZ];
__device__ __align__(128) __half g_F_h[F_SZ];
__device__ __align__(128) __half g_H_h[H_SZ];
__device__ __align__(128) __half g_xr_h[XSP_SZ];
__device__ __align__(128) __half g_xi_h[XSP_SZ];
__device__ __align__(128) __half g_G_h[G2_SZ];
__device__ __align__(128) __half g_mA_h[XS_SZ];
__device__ __align__(128) __half g_mB_h[XS_SZ];
__device__ __align__(128) __half g_dc_h[DCS_SZ];
__device__ __align__(128) __half g_d2_h[D2_SZ];
__device__ __align__(128) __half g_wt_h[4*C_*C_];
__device__ __align__(128) float g_grids[XS_SZ];
__device__ float g_lsc16[L_];
__device__ float g_cscale[2];        // {1/16, 1/4096}
__device__ float g_part[2][1024][C_];
__device__ float g_mu[C_], g_rstd[C_];

__device__ __forceinline__ float gelu_f(float v){
    return 0.5f*v*(1.0f + erff(v*0.7071067811865476f));
}
__device__ __forceinline__ unsigned smem_u32(const void* p){
    unsigned a;
    asm("{ .reg .u64 t; cvta.to.shared.u64 t, %1; cvt.u32.u64 %0, t; }" : "=r"(a) : "l"(p));
    return a;
}
__device__ __forceinline__ int swadr(int r, int w){
    return r*64 + ((((w>>2) ^ ((r>>1)&3))) << 4) + ((w & 3) << 2);
}
__device__ __forceinline__ void cpa16(unsigned saddr, const void* g, bool v){
    asm volatile("cp.async.cg.shared.global [%0], [%1], 16, %2;"
                 :: "r"(saddr), "l"(g), "r"(v ? 16 : 0));
}
#define CP_COMMIT() asm volatile("cp.async.commit_group;")
#define LDMX4(r0,r1,r2,r3,addr) \
    asm volatile("ldmatrix.sync.aligned.m8n8.x4.shared.b16 {%0,%1,%2,%3}, [%4];" \
        : "=r"(r0),"=r"(r1),"=r"(r2),"=r"(r3) : "r"(addr))
#define MMA_OP(cc, aa, bb) asm volatile( \
    "mma.sync.aligned.m16n8k16.row.col.f32.f16.f16.f32 " \
    "{%0,%1,%2,%3},{%4,%5,%6,%7},{%8,%9},{%0,%1,%2,%3};" \
    : "+f"(cc[0]),"+f"(cc[1]),"+f"(cc[2]),"+f"(cc[3]) \
    : "r"(aa[0]),"r"(aa[1]),"r"(aa[2]),"r"(aa[3]),"r"(bb[0]),"r"(bb[1]))

// ---------------- prep kernels ----------------
__global__ void p_xT2(const float* __restrict__ x){
    __shared__ float sm[32][33];
    int j  = blockIdx.y;
    int tc = blockIdx.x & 7;
    int tn = blockIdx.x >> 3;
    int tx = threadIdx.x, ty = threadIdx.y;
    #pragma unroll
    for (int k=0;k<4;k++){
        int c = tc*32 + ty + k*8;
        size_t offx = (size_t)c*S_ + (size_t)j*NLON_ + tn*32 + tx;
        float v = x[offx];
        sm[ty+k*8][tx] = v;
        g_x_h[offx] = __float2half_rn(v);
    }
    __syncthreads();
    #pragma unroll
    for (int k=0;k<4;k++){
        int n = tn*32 + ty + k*8;
        int c = tc*32 + tx;
        size_t off = ((size_t)n*NLAT_ + j)*C_ + c;
        g_xt_h[off] = __float2half_rn(sm[tx][ty+k*8]);
    }
}
// Nyquist column: F[re][256][c][j] = sum_n x*(-1)^n ; F[im][256] = 0
__global__ void p_nyq(){
    int gw   = blockIdx.x*8 + (threadIdx.x >> 5);
    int lane = threadIdx.x & 31;
    const __half2* xr = (const __half2*)(g_x_h + (size_t)gw*NLON_);
    float s = 0.f;
    #pragma unroll 4
    for (int k = lane; k < 256; k += 32){
        float2 v = __half22float2(xr[k]);
        s += v.x - v.y;
    }
    #pragma unroll
    for (int o=16;o>0;o>>=1) s += __shfl_xor_sync(0xffffffffu, s, o);
    if (lane == 0){
        g_F_h[(size_t)256*C_*NLAT_ + gw] = __float2half_rn(s);
        g_F_h[(size_t)M_*C_*NLAT_ + (size_t)256*C_*NLAT_ + gw] = __float2half_rn(0.f);
    }
}
__global__ void p_lw(const float* __restrict__ leg, const float* __restrict__ wq){
    size_t i4 = ((size_t)blockIdx.x*256 + threadIdx.x)*4;
    if (i4 >= LW_SZ) return;
    float4 v = *(const float4*)(leg + i4);
    int w0 = (int)(i4 & (NLAT_-1));
    float a = 16.f*v.x*wq[w0],   b = 16.f*v.y*wq[w0+1];
    float c = 16.f*v.z*wq[w0+2], d = 16.f*v.w*wq[w0+3];
    __half2* o = (__half2*)(g_lw_h + i4);
    o[0] = __floats2half2_rn(a, b);
    o[1] = __floats2half2_rn(c, d);
}
__global__ void p_legT(const float* __restrict__ leg){
    __shared__ float sm[32][33];
    int m  = blockIdx.y;
    int tl = blockIdx.x & 7;
    int tj = blockIdx.x >> 3;
    int tx = threadIdx.x, ty = threadIdx.y;
    #pragma unroll
    for (int k=0;k<4;k++){
        int l = tl*32 + ty + k*8;
        sm[ty+k*8][tx] = leg[(size_t)l*M_*NLAT_ + (size_t)m*NLAT_ + tj*32 + tx];
    }
    __syncthreads();
    #pragma unroll
    for (int k=0;k<4;k++){
        int j = tj*32 + ty + k*8;
        int l = tl*32 + tx;
        size_t off = ((size_t)m*NLAT_ + j)*L_ + l;
        g_lg_h[off] = __float2half_rn(16.0f*sm[tx][ty+k*8]);
    }
}
__global__ void p_W2(const float* __restrict__ wr, const float* __restrict__ wi){
    __shared__ float sr[256][8], si[256][8];
    int f  = blockIdx.y;
    int l0 = blockIdx.x * 16;
    int c  = threadIdx.x;
    int i0min = (l0*(NREF_-1)) / (L_-1);
    if (i0min > NREF_-8) i0min = NREF_-8;
    size_t rb = ((size_t)f*C_ + c)*NREF_ + i0min;
    #pragma unroll
    for (int k=0;k<8;k++){ sr[c][k] = wr[rb+k]; si[c][k] = wi[rb+k]; }
    __syncthreads();
    #pragma unroll 4
    for (int li=0; li<16; li++){
        int l = l0 + li;
        float pos = (float)(l*(NREF_-1)) / (float)(L_-1);
        int i0 = (int)floorf(pos);
        if (i0 > NREF_-2) i0 = NREF_-2;
        float fr = pos - (float)i0;
        int k = i0 - i0min;
        float vre = sr[c][k]*(1.0f-fr) + sr[c][k+1]*fr;
        float vim = si[c][k]*(1.0f-fr) + si[c][k+1]*fr;
        size_t ob = ((size_t)l*C_ + f)*K2C_;
        g_wr_h[ob + c]      = __float2half_rn( vre);
        g_wr_h[ob + C_ + c] = __float2half_rn(-vim);
        g_wi_h[ob + c]      = __float2half_rn( vim);
        g_wi_h[ob + C_ + c] = __float2half_rn( vre);
    }
}
// S3 m=256 column: xs[256][f][l] = lsc16[l] * sum_c A[l][f][c]*H[l][256][c]
__global__ void p_s3col(){
    int bz = blockIdx.x;
    int l  = bz & (L_-1);
    bool im = bz >= L_;
    const __half* A = (im ? g_wi_h : g_wr_h) + (size_t)l*C_*K2C_;
    __half* O = (im ? g_xi_h : g_xr_h) + (size_t)256*C_*L_ + l;
    __shared__ __half2 sh[256];
    const __half2* Hrow = (const __half2*)(g_H_h + (size_t)l*M_*K2C_ + (size_t)256*K2C_);
    sh[threadIdx.x] = Hrow[threadIdx.x];
    __syncthreads();
    int f = threadIdx.x;
    const __half2* Ar = (const __half2*)(A + (size_t)f*K2C_);
    float s = 0.f;
    #pragma unroll 8
    for (int c2=0; c2<256; c2++){
        float2 a = __half22float2(Ar[c2]);
        float2 h = __half22float2(sh[c2]);
        s += a.x*h.x + a.y*h.y;
    }
    O[(size_t)f*L_] = __float2half_rn(s * g_lsc16[l]);
}
__global__ void p_dft(){
    int i = blockIdx.x*256 + threadIdx.x;
    if (i < L_) g_lsc16[i] = sqrtf(1.0f + (float)i) * (1.0f/(float)C_) * (1.0f/16.0f);
    if (i < 2)  g_cscale[i] = (i==0) ? 0.0625f : (1.0f/4096.0f);
    if (i < (int)DCS_SZ){
        int n = i & 511;
        int m = (i >> 9) % M_;
        int ri = i / (M_*NLON_);
        int a = (m*n) & 511;
        float ang = (float)a * (1.0f/256.0f);
        float v = ri ? -sinpif(ang) : cospif(ang);
        g_dc_h[i] = __float2half_rn(v);
    }
    if (i < (int)D2_SZ){
        int mp = i % MP_;
        int n  = i / MP_;
        float v = 0.f;
        if (mp < M_){
            float wm = (mp==0 || mp==M_-1) ? 1.0f : 2.0f;
            int a = (mp*n) & 511;
            v = wm * cospif((float)a*(1.0f/256.0f)) * 0.5f;
        } else if (mp < 2*M_){
            int m2 = mp - M_;
            float wm = (m2==0 || m2==M_-1) ? 1.0f : 2.0f;
            int a = (m2*n) & 511;
            v = -wm * sinpif((float)a*(1.0f/256.0f)) * 0.5f;
        }
        g_d2_h[i] = __float2half_rn(v);
    }
}
__global__ void p_wT(const float* w1, const float* w2, const float* w3, const float* w4){
    int i = blockIdx.x*256 + threadIdx.x;
    if (i >= C_*C_) return;
    int c = i / C_, cp = i % C_;
    const float* ws[4] = {w1, w2, w3, w4};
    #pragma unroll
    for (int k=0;k<4;k++)
        g_wt_h[(size_t)k*C_*C_ + (size_t)cp*C_ + c] = __float2half_rn(16.0f*ws[k][i]);
}
__global__ void p_zeroG2(){
    int i = blockIdx.x*256 + threadIdx.x;
    int nz = MP_ - 514;
    int tot = NLAT_*C_*nz;
    if (i >= tot) return;
    int k  = i % nz;
    int jf = i / nz;
    g_G_h[(size_t)jf*MP_ + 514 + k] = __float2half_rn(0.f);
}

// ---------------- pipelined mma.sync fp16 GEMM ----------------
#define STGB 24576
#define NSTG 3
#define SMEM_DYN (NSTG*STGB)

template<int ACT, int DONORM>
__global__ __launch_bounds__(256, 2) void mmagemm(
    const __half* __restrict__ Ah,
    const __half* __restrict__ Bh,
    const __half* __restrict__ Ah2,
    const __half* __restrict__ Bh2, __half* __restrict__ Oh2,
    int zsplit,
    float* __restrict__ Dout,
    __half* __restrict__ Oh,
    const float* __restrict__ biasJ, const float* __restrict__ bscale,
    const float* __restrict__ addsrc,
    int Mrows, int Ncols, int K,
    long sAi, long sAb, long sBi, long sBb,
    long sCi, long sCj, long sCb)
{
    extern __shared__ char dsm[];
    const unsigned sb = smem_u32(dsm);

    const int t    = threadIdx.x;
    const int lane = t & 31;
    const int warp = t >> 5;
    const int g    = lane >> 2;
    const int tig  = lane & 3;
    const int mm   = lane >> 3;
    const int rrl  = lane & 7;
    const int wm   = warp >> 2;
    const int wn   = warp & 3;
    int bz = blockIdx.z;
    if (bz >= zsplit){
        bz -= zsplit;
        if (Ah2){ Ah = Ah2; }
        if (Bh2){ Bh = Bh2; }
        if (Oh2){ Oh = Oh2; }
    }
    const long i0  = (long)blockIdx.y * 128;
    const long j0  = (long)blockIdx.x * 128;

    const __half* Ahb = Ah + (long)bz*sAb;
    const __half* Bhb = Bh + (long)bz*sBb;

    const int row   = t >> 1;
    const int half  = t & 1;
    const long arow = i0 + row;
    const long brow = j0 + row;
    const bool bok  = brow < (long)Ncols;
    const long aoff = arow * sAi;
    const long boff = brow * sBi;

    float acc[64];
    #pragma unroll
    for (int i=0;i<64;i++) acc[i] = 0.f;

    auto load_stage = [&](int ks, int s){
        unsigned st = sb + s*STGB;
        long kg = (long)ks*32;
        #pragma unroll
        for (int q=0;q<2;q++){
            int c = half*2 + q;
            long ke = kg + c*8;
            unsigned so = (unsigned)(row*64 + ((c ^ ((row>>1)&3)) << 4));
            cpa16(st + so,          Ahb + aoff + ke, true);
            cpa16(st + 16384 + so,  Bhb + boff + ke, bok);
        }
    };

    const int nk = K >> 5;
    load_stage(0, 0);
    CP_COMMIT();
    if (nk > 1){ load_stage(1, 1); }
    CP_COMMIT();

    for (int ks = 0; ks < nk; ks++){
        if (ks + 1 < nk) asm volatile("cp.async.wait_group 1;");
        else             asm volatile("cp.async.wait_group 0;");
        __syncthreads();

        const unsigned sA = sb + (ks % NSTG)*STGB;
        const unsigned sB = sA + 16384;
        #pragma unroll
        for (int kk=0; kk<2; kk++){
            unsigned ah[4][4], bh[4][2];
            #pragma unroll
            for (int p=0;p<2;p++){
                int rowB = wn*32 + (p*2 + (mm>>1))*8 + rrl;
                int wB   = kk*8 + (mm&1)*4;
                unsigned ad = sB + (unsigned)swadr(rowB, wB);
                LDMX4(bh[p*2][0], bh[p*2][1], bh[p*2+1][0], bh[p*2+1][1], ad);
            }
            #pragma unroll
            for (int mt=0; mt<4; mt++){
                int rowA = wm*64 + mt*16 + (mm&1)*8 + rrl;
                int wA   = kk*8 + (mm>>1)*4;
                unsigned ad = sA + (unsigned)swadr(rowA, wA);
                LDMX4(ah[mt][0], ah[mt][1], ah[mt][2], ah[mt][3], ad);
            }
            #pragma unroll
            for (int mt=0; mt<4; mt++)
                #pragma unroll
                for (int nt=0; nt<4; nt++) MMA_OP((&acc[(mt*4+nt)*4]), ah[mt], bh[nt]);
        }
        if (ks + 2 < nk){
            load_stage(ks+2, (ks+2) % NSTG);
        }
        CP_COMMIT();
    }

    // ---------------- epilogue ----------------
    float scl = bscale ? bscale[bz] : 1.0f;
    float csum[DONORM ? 8 : 1], csq[DONORM ? 8 : 1];
    if (DONORM){
        #pragma unroll
        for (int i=0;i<8;i++){ csum[i]=0.f; csq[i]=0.f; }
    }

    #pragma unroll
    for (int mt=0; mt<4; mt++){
        long rA = i0 + wm*64 + mt*16 + g;
        #pragma unroll
        for (int nt=0; nt<4; nt++){
            long cB = j0 + wn*32 + nt*8 + 2*tig;
            float* a = &acc[(mt*4+nt)*4];
            #pragma unroll
            for (int h2=0; h2<2; h2++){
                long rowg = rA + h2*8;
                if (rowg >= (long)Mrows) continue;
                long offr = (long)bz*sCb + rowg*sCi;
                if (sCj == 1 && cB + 1 < (long)Ncols){
                    float v0 = a[h2*2+0] * scl;
                    float v1 = a[h2*2+1] * scl;
                    if (biasJ){ v0 += biasJ[cB]; v1 += biasJ[cB+1]; }
                    if (ACT == 1){ v0 = gelu_f(v0); v1 = gelu_f(v1); }
                    long off = offr + cB;
                    if (addsrc){ v0 += addsrc[off]; v1 += addsrc[off+1]; }
                    if (Dout) *(float2*)(Dout + off) = make_float2(v0, v1);
                    if (Oh)   *(__half2*)(Oh + off) = __floats2half2_rn(v0, v1);
                    if (DONORM){
                        csum[nt*2]   += v0; csq[nt*2]   += v0*v0;
                        csum[nt*2+1] += v1; csq[nt*2+1] += v1*v1;
                    }
                } else {
                    #pragma unroll
                    for (int q=0; q<2; q++){
                        long col = cB + q;
                        if (col >= (long)Ncols) continue;
                        float v = a[h2*2+q] * scl;
                        if (biasJ) v += biasJ[col];
                        if (ACT == 1) v = gelu_f(v);
                        long off = offr + col*sCj;
                        if (addsrc) v += addsrc[off];
                        if (Dout) Dout[off] = v;
                        if (Oh)   Oh[off] = __float2half_rn(v);
                    }
                }
            }
        }
    }

    if (DONORM){
        float* ssum = (float*)dsm;
        float* ssq  = ssum + 128;
        __syncthreads();
        if (t < 128){ ssum[t] = 0.f; ssq[t] = 0.f; }
        __syncthreads();
        #pragma unroll
        for (int i=0;i<8;i++){
            int cl = wn*32 + (i>>1)*8 + 2*tig + (i&1);
            atomicAdd(&ssum[cl], csum[i]);
            atomicAdd(&ssq[cl],  csq[i]);
        }
        __syncthreads();
        if (t < 128){
            g_part[0][blockIdx.y][j0 + t] = ssum[t];
            g_part[1][blockIdx.y][j0 + t] = ssq[t];
        }
    }
}

// ---------------- norm + finalize ----------------
__global__ void norm2_k(){
    int c = threadIdx.x;
    float s=0.f, q=0.f;
    for (int b=0;b<1024;b++){ s += g_part[0][b][c]; q += g_part[1][b][c]; }
    float mu = s * (1.0f/(float)S_);
    float var = q * (1.0f/(float)S_) - mu*mu;
    g_mu[c] = mu;
    g_rstd[c] = rsqrtf(var + 1e-3f);
}
__global__ void fin_k(const float* __restrict__ x,
                      const float* __restrict__ gamma,
                      const float* __restrict__ beta,
                      float* __restrict__ out){
    __shared__ float sm[32][33];
    int j  = blockIdx.y;
    int tc = blockIdx.x & 7;
    int tn = blockIdx.x >> 3;
    int tx = threadIdx.x, ty = threadIdx.y;
    #pragma unroll
    for (int k=0;k<4;k++){
        int n = tn*32 + ty + k*8;
        sm[ty+k*8][tx] = g_grids[((size_t)n*NLAT_ + j)*C_ + tc*32 + tx];
    }
    __syncthreads();
    #pragma unroll
    for (int k=0;k<4;k++){
        int c = tc*32 + ty + k*8;
        int n = tn*32 + tx;
        size_t off = (size_t)c*S_ + (size_t)j*NLON_ + n;
        float v = sm[tx][ty+k*8];
        out[off] = (v - g_mu[c])*g_rstd[c]*gamma[c] + beta[c] + x[off];
    }
}

// ---------------- host side ----------------
#define DEVPTR(T, var, sym) T* var; cudaGetSymbolAddress((void**)&var, sym)

static void launch_gemm(int act, int donorm, dim3 grid,
    const __half* Ah, const __half* Bh,
    const __half* Ah2, const __half* Bh2, __half* Oh2, int zsplit,
    float* Dout, __half* Oh,
    const float* biasJ, const float* bscale, const float* addsrc,
    int M, int N, int K,
    long sAi, long sAb, long sBi, long sBb, long sCi, long sCj, long sCb)
{
    if (donorm)
        mmagemm<1,1><<<grid,256,SMEM_DYN>>>(Ah,Bh,Ah2,Bh2,Oh2,zsplit,
            Dout,Oh,biasJ,bscale,addsrc,M,N,K,sAi,sAb,sBi,sBb,sCi,sCj,sCb);
    else if (act)
        mmagemm<1,0><<<grid,256,SMEM_DYN>>>(Ah,Bh,Ah2,Bh2,Oh2,zsplit,
            Dout,Oh,biasJ,bscale,addsrc,M,N,K,sAi,sAb,sBi,sBb,sCi,sCj,sCb);
    else
        mmagemm<0,0><<<grid,256,SMEM_DYN>>>(Ah,Bh,Ah2,Bh2,Oh2,zsplit,
            Dout,Oh,biasJ,bscale,addsrc,M,N,K,sAi,sAb,sBi,sBb,sCi,sCj,sCb);
}

extern "C" void kernel_launch(void* const* d_in, const int* in_sizes, int n_in,
                              void* d_out, int out_size){
    const float* x      = (const float*)d_in[0];
    const float* leg    = (const float*)d_in[1];
    const float* wquad  = (const float*)d_in[2];
    const float* w_real = (const float*)d_in[3];
    const float* w_imag = (const float*)d_in[4];
    const float* m1w1   = (const float*)d_in[5];
    const float* m1b1   = (const float*)d_in[6];
    const float* m1w2   = (const float*)d_in[7];
    const float* m1b2   = (const float*)d_in[8];
    const float* m2w1   = (const float*)d_in[9];
    const float* m2b1   = (const float*)d_in[10];
    const float* m2w2   = (const float*)d_in[11];
    const float* m2b2   = (const float*)d_in[12];
    const float* gamma  = (const float*)d_in[13];
    const float* beta   = (const float*)d_in[14];
    float* out = (float*)d_out;

    cudaFuncSetAttribute(mmagemm<0,0>, cudaFuncAttributeMaxDynamicSharedMemorySize, SMEM_DYN);
    cudaFuncSetAttribute(mmagemm<1,0>, cudaFuncAttributeMaxDynamicSharedMemorySize, SMEM_DYN);
    cudaFuncSetAttribute(mmagemm<1,1>, cudaFuncAttributeMaxDynamicSharedMemorySize, SMEM_DYN);

    DEVPTR(__half, xh, g_x_h);
    DEVPTR(__half, xth,g_xt_h);
    DEVPTR(__half, lwh,g_lw_h);
    DEVPTR(__half, lgh,g_lg_h);
    DEVPTR(__half, wrh,g_wr_h);
    DEVPTR(__half, wih,g_wi_h);
    DEVPTR(__half, Fh, g_F_h);
    DEVPTR(__half, Hh, g_H_h);
    DEVPTR(__half, xrh,g_xr_h);
    DEVPTR(__half, xih,g_xi_h);
    DEVPTR(__half, Gh, g_G_h);
    DEVPTR(__half, mAh,g_mA_h);
    DEVPTR(__half, mBh,g_mB_h);
    DEVPTR(__half, dch,g_dc_h);
    DEVPTR(__half, d2h,g_d2_h);
    DEVPTR(__half, wth,g_wt_h);
    DEVPTR(float, grids, g_grids);
    DEVPTR(float, lsc16, g_lsc16);
    DEVPTR(float, cscale, g_cscale);

    const int BIGZ = 1 << 30;

    // ---- prep ----
    p_dft <<<(unsigned)((D2_SZ+255)/256), 256>>>();
    p_xT2 <<<dim3(128, NLAT_), dim3(32,8)>>>(x);

    // ---- S1: rfft DFT-GEMM, N=256 -> F (ri,m,c,j) ----
    launch_gemm(0, 0, dim3(2, 512, 2),
        xh, dch, nullptr, nullptr, nullptr, BIGZ,
        nullptr, Fh, nullptr, nullptr, nullptr,
        C_*NLAT_, 256, NLON_,
        NLON_, 0, NLON_, (long)M_*NLON_,
        1, (long)C_*NLAT_, (long)M_*C_*NLAT_);
    p_nyq <<<8192, 256>>>();

    p_lw     <<<(unsigned)((LW_SZ/4+255)/256), 256>>>(leg, wquad);
    p_legT   <<<dim3(64, M_), dim3(32,8)>>>(leg);
    p_W2     <<<dim3(16, 256), 256>>>(w_real, w_imag);
    p_wT     <<<(C_*C_+255)/256, 256>>>(m1w1, m1w2, m2w1, m2w2);
    p_zeroG2 <<<(unsigned)((NLAT_*C_*(MP_-514)+255)/256), 256>>>();

    // ---- S2 merged (batch 2M): A=16*lw; B/out switch at zsplit=M ----
    launch_gemm(0, 0, dim3(2, 2, 2*M_),
        lwh, Fh,
        nullptr, Fh + M_*(size_t)C_*NLAT_, Hh + C_, M_,
        nullptr, Hh, nullptr, nullptr, nullptr,
        L_, C_, NLAT_,
        (long)M_*NLAT_, NLAT_, NLAT_, (long)C_*NLAT_,
        (long)M_*K2C_, 1, K2C_);

    // ---- S3 merged (batch 2L), N=256; A/out switch at zsplit=L ----
    launch_gemm(0, 0, dim3(2, 2, 2*L_),
        wrh, Hh,
        wih, nullptr, xih, L_,
        nullptr, xrh, nullptr, lsc16, nullptr,
        C_, 256, K2C_,
        K2C_, (long)C_*K2C_, K2C_, (long)M_*K2C_,
        L_, (long)C_*L_, 1);
    p_s3col <<<2*L_, 256>>>();

    // ---- S4 merged (batch 2M): A=16*lgT; B/out switch at zsplit=M ----
    launch_gemm(0, 0, dim3(2, 2, 2*M_),
        lgh, xrh,
        nullptr, xih, Gh + M_, M_,
        nullptr, Gh, nullptr, nullptr, nullptr,
        NLAT_, C_, L_,
        L_, (long)NLAT_*L_, L_, (long)C_*L_,
        (long)C_*MP_, MP_, 1);

    // ---- S5: irfft + GELU -> fp32 grids (n,j,f) ----
    launch_gemm(1, 0, dim3(512, 4, 1),
        d2h, Gh, nullptr, nullptr, nullptr, BIGZ,
        grids, nullptr, nullptr, cscale+1, nullptr,
        NLON_, NLAT_*C_, MP_,
        MP_, 0, MP_, 0,
        (long)NLAT_*C_, 1, 0);

    // ---- MLPs (single-pass): B = 16*wT, bscale = 1/16 ----
    launch_gemm(1, 0, dim3(2, 1024, 1),
        xth, wth + 0, nullptr, nullptr, nullptr, BIGZ,
        nullptr, mAh, m1b1, cscale, nullptr,
        S_, C_, C_, C_, 0, C_, 0, C_, 1, 0);
    launch_gemm(1, 0, dim3(2, 1024, 1),
        mAh, wth + C_*C_, nullptr, nullptr, nullptr, BIGZ,
        nullptr, mBh, m1b2, cscale, grids,
        S_, C_, C_, C_, 0, C_, 0, C_, 1, 0);
    launch_gemm(1, 0, dim3(2, 1024, 1),
        mBh, wth + 2*C_*C_, nullptr, nullptr, nullptr, BIGZ,
        nullptr, mAh, m2b1, cscale, nullptr,
        S_, C_, C_, C_, 0, C_, 0, C_, 1, 0);
    // MLP4 with fused norm partial reduction (separate instantiation)
    launch_gemm(1, 1, dim3(2, 1024, 1),
        mAh, wth + 3*C_*C_, nullptr, nullptr, nullptr, BIGZ,
        grids, nullptr, m2b2, cscale, nullptr,
        S_, C_, C_, C_, 0, C_, 0, C_, 1, 0);

    // ---- instance norm + residual + transpose out ----
    norm2_k<<<1, 256>>>();
    fin_k<<<dim3(128, NLAT_), dim3(32,8)>>>(x, gamma, beta, out);
}

// round 15
// speedup vs baseline: 1.0671x; 1.0671x over previous
#include <cuda_runtime.h>
#include <cuda_fp16.h>
#include <math.h>

#define C_    256
#define NLAT_ 256
#define NLON_ 512
#define L_    256
#define M_    257
#define NREF_ 64
#define S_    (NLAT_*NLON_)
#define K2C_  512
#define MP_   544               // 2*M=514 padded to mult of 32

#define XS_SZ   ((size_t)C_*S_)
#define LW_SZ   ((size_t)L_*M_*NLAT_)
#define LGT_SZ  ((size_t)M_*NLAT_*L_)
#define WC_SZ   ((size_t)L_*C_*K2C_)
#define F_SZ    ((size_t)2*M_*C_*NLAT_)
#define H_SZ    ((size_t)L_*M_*K2C_)
#define XSP_SZ  ((size_t)M_*C_*L_)
#define G2_SZ   ((size_t)NLAT_*C_*MP_)
#define DCS_SZ  ((size_t)2*M_*NLON_)
#define D2_SZ   ((size_t)NLON_*MP_)

__device__ __align__(128) __half g_x_h[XS_SZ];
__device__ __align__(128) __half g_xt_h[XS_SZ];
__device__ __align__(128) __half g_lw_h[LW_SZ];
__device__ __align__(128) __half g_lg_h[LGT_SZ];
__device__ __align__(128) __half g_wr_h[WC_SZ];
__device__ __align__(128) __half g_wi_h[WC_SZ];
__device__ __align__(128) __half g_F_h[F_SZ];
__device__ __align__(128) __half g_H_h[H_SZ];
__device__ __align__(128) __half g_xr_h[XSP_SZ];
__device__ __align__(128) __half g_xi_h[XSP_SZ];
__device__ __align__(128) __half g_G_h[G2_SZ];
__device__ __align__(128) __half g_mA_h[XS_SZ];
__device__ __align__(128) __half g_mB_h[XS_SZ];
__device__ __align__(128) __half g_dc_h[DCS_SZ];
__device__ __align__(128) __half g_d2_h[D2_SZ];
__device__ __align__(128) __half g_wt_h[4*C_*C_];
__device__ __align__(128) float g_grids[XS_SZ];
__device__ float g_lsc16[L_];
__device__ float g_cscale[2];        // {1/16, 1/4096}
__device__ float g_part[2][1024][C_];
__device__ float g_mu[C_], g_rstd[C_];

__device__ __forceinline__ float gelu_f(float v){
    return 0.5f*v*(1.0f + erff(v*0.7071067811865476f));
}
__device__ __forceinline__ unsigned smem_u32(const void* p){
    unsigned a;
    asm("{ .reg .u64 t; cvta.to.shared.u64 t, %1; cvt.u32.u64 %0, t; }" : "=r"(a) : "l"(p));
    return a;
}
__device__ __forceinline__ int swadr(int r, int w){
    return r*64 + ((((w>>2) ^ ((r>>1)&3))) << 4) + ((w & 3) << 2);
}
__device__ __forceinline__ void cpa16(unsigned saddr, const void* g, bool v){
    asm volatile("cp.async.cg.shared.global [%0], [%1], 16, %2;"
                 :: "r"(saddr), "l"(g), "r"(v ? 16 : 0));
}
#define CP_COMMIT() asm volatile("cp.async.commit_group;")
#define LDMX4(r0,r1,r2,r3,addr) \
    asm volatile("ldmatrix.sync.aligned.m8n8.x4.shared.b16 {%0,%1,%2,%3}, [%4];" \
        : "=r"(r0),"=r"(r1),"=r"(r2),"=r"(r3) : "r"(addr))
#define MMA_OP(cc, aa, bb) asm volatile( \
    "mma.sync.aligned.m16n8k16.row.col.f32.f16.f16.f32 " \
    "{%0,%1,%2,%3},{%4,%5,%6,%7},{%8,%9},{%0,%1,%2,%3};" \
    : "+f"(cc[0]),"+f"(cc[1]),"+f"(cc[2]),"+f"(cc[3]) \
    : "r"(aa[0]),"r"(aa[1]),"r"(aa[2]),"r"(aa[3]),"r"(bb[0]),"r"(bb[1]))

// ---------------- prep kernels ----------------
__global__ void p_xT2(const float* __restrict__ x){
    __shared__ float sm[32][33];
    int j  = blockIdx.y;
    int tc = blockIdx.x & 7;
    int tn = blockIdx.x >> 3;
    int tx = threadIdx.x, ty = threadIdx.y;
    #pragma unroll
    for (int k=0;k<4;k++){
        int c = tc*32 + ty + k*8;
        size_t offx = (size_t)c*S_ + (size_t)j*NLON_ + tn*32 + tx;
        float v = x[offx];
        sm[ty+k*8][tx] = v;
        g_x_h[offx] = __float2half_rn(v);
    }
    __syncthreads();
    #pragma unroll
    for (int k=0;k<4;k++){
        int n = tn*32 + ty + k*8;
        int c = tc*32 + tx;
        size_t off = ((size_t)n*NLAT_ + j)*C_ + c;
        g_xt_h[off] = __float2half_rn(sm[tx][ty+k*8]);
    }
}
__global__ void p_nyq(){
    int gw   = blockIdx.x*8 + (threadIdx.x >> 5);
    int lane = threadIdx.x & 31;
    const __half2* xr = (const __half2*)(g_x_h + (size_t)gw*NLON_);
    float s = 0.f;
    #pragma unroll 4
    for (int k = lane; k < 256; k += 32){
        float2 v = __half22float2(xr[k]);
        s += v.x - v.y;
    }
    #pragma unroll
    for (int o=16;o>0;o>>=1) s += __shfl_xor_sync(0xffffffffu, s, o);
    if (lane == 0){
        g_F_h[(size_t)256*C_*NLAT_ + gw] = __float2half_rn(s);
        g_F_h[(size_t)M_*C_*NLAT_ + (size_t)256*C_*NLAT_ + gw] = __float2half_rn(0.f);
    }
}
__global__ void p_lw(const float* __restrict__ leg, const float* __restrict__ wq){
    size_t i4 = ((size_t)blockIdx.x*256 + threadIdx.x)*4;
    if (i4 >= LW_SZ) return;
    float4 v = *(const float4*)(leg + i4);
    int w0 = (int)(i4 & (NLAT_-1));
    float a = 16.f*v.x*wq[w0],   b = 16.f*v.y*wq[w0+1];
    float c = 16.f*v.z*wq[w0+2], d = 16.f*v.w*wq[w0+3];
    __half2* o = (__half2*)(g_lw_h + i4);
    o[0] = __floats2half2_rn(a, b);
    o[1] = __floats2half2_rn(c, d);
}
__global__ void p_legT(const float* __restrict__ leg){
    __shared__ float sm[32][33];
    int m  = blockIdx.y;
    int tl = blockIdx.x & 7;
    int tj = blockIdx.x >> 3;
    int tx = threadIdx.x, ty = threadIdx.y;
    #pragma unroll
    for (int k=0;k<4;k++){
        int l = tl*32 + ty + k*8;
        sm[ty+k*8][tx] = leg[(size_t)l*M_*NLAT_ + (size_t)m*NLAT_ + tj*32 + tx];
    }
    __syncthreads();
    #pragma unroll
    for (int k=0;k<4;k++){
        int j = tj*32 + ty + k*8;
        int l = tl*32 + tx;
        size_t off = ((size_t)m*NLAT_ + j)*L_ + l;
        g_lg_h[off] = __float2half_rn(16.0f*sm[tx][ty+k*8]);
    }
}
__global__ void p_W2(const float* __restrict__ wr, const float* __restrict__ wi){
    __shared__ float sr[256][8], si[256][8];
    int f  = blockIdx.y;
    int l0 = blockIdx.x * 16;
    int c  = threadIdx.x;
    int i0min = (l0*(NREF_-1)) / (L_-1);
    if (i0min > NREF_-8) i0min = NREF_-8;
    size_t rb = ((size_t)f*C_ + c)*NREF_ + i0min;
    #pragma unroll
    for (int k=0;k<8;k++){ sr[c][k] = wr[rb+k]; si[c][k] = wi[rb+k]; }
    __syncthreads();
    #pragma unroll 4
    for (int li=0; li<16; li++){
        int l = l0 + li;
        float pos = (float)(l*(NREF_-1)) / (float)(L_-1);
        int i0 = (int)floorf(pos);
        if (i0 > NREF_-2) i0 = NREF_-2;
        float fr = pos - (float)i0;
        int k = i0 - i0min;
        float vre = sr[c][k]*(1.0f-fr) + sr[c][k+1]*fr;
        float vim = si[c][k]*(1.0f-fr) + si[c][k+1]*fr;
        size_t ob = ((size_t)l*C_ + f)*K2C_;
        g_wr_h[ob + c]      = __float2half_rn( vre);
        g_wr_h[ob + C_ + c] = __float2half_rn(-vim);
        g_wi_h[ob + c]      = __float2half_rn( vim);
        g_wi_h[ob + C_ + c] = __float2half_rn( vre);
    }
}
__global__ void p_s3col(){
    int bz = blockIdx.x;
    int l  = bz & (L_-1);
    bool im = bz >= L_;
    const __half* A = (im ? g_wi_h : g_wr_h) + (size_t)l*C_*K2C_;
    __half* O = (im ? g_xi_h : g_xr_h) + (size_t)256*C_*L_ + l;
    __shared__ __half2 sh[256];
    const __half2* Hrow = (const __half2*)(g_H_h + (size_t)l*M_*K2C_ + (size_t)256*K2C_);
    sh[threadIdx.x] = Hrow[threadIdx.x];
    __syncthreads();
    int f = threadIdx.x;
    const __half2* Ar = (const __half2*)(A + (size_t)f*K2C_);
    float s = 0.f;
    #pragma unroll 8
    for (int c2=0; c2<256; c2++){
        float2 a = __half22float2(Ar[c2]);
        float2 h = __half22float2(sh[c2]);
        s += a.x*h.x + a.y*h.y;
    }
    O[(size_t)f*L_] = __float2half_rn(s * g_lsc16[l]);
}
__global__ void p_dft(){
    int i = blockIdx.x*256 + threadIdx.x;
    if (i < L_) g_lsc16[i] = sqrtf(1.0f + (float)i) * (1.0f/(float)C_) * (1.0f/16.0f);
    if (i < 2)  g_cscale[i] = (i==0) ? 0.0625f : (1.0f/4096.0f);
    if (i < (int)DCS_SZ){
        int n = i & 511;
        int m = (i >> 9) % M_;
        int ri = i / (M_*NLON_);
        int a = (m*n) & 511;
        float ang = (float)a * (1.0f/256.0f);
        float v = ri ? -sinpif(ang) : cospif(ang);
        g_dc_h[i] = __float2half_rn(v);
    }
    if (i < (int)D2_SZ){
        int mp = i % MP_;
        int n  = i / MP_;
        float v = 0.f;
        if (mp < M_){
            float wm = (mp==0 || mp==M_-1) ? 1.0f : 2.0f;
            int a = (mp*n) & 511;
            v = wm * cospif((float)a*(1.0f/256.0f)) * 0.5f;
        } else if (mp < 2*M_){
            int m2 = mp - M_;
            float wm = (m2==0 || m2==M_-1) ? 1.0f : 2.0f;
            int a = (m2*n) & 511;
            v = -wm * sinpif((float)a*(1.0f/256.0f)) * 0.5f;
        }
        g_d2_h[i] = __float2half_rn(v);
    }
}
__global__ void p_wT(const float* w1, const float* w2, const float* w3, const float* w4){
    int i = blockIdx.x*256 + threadIdx.x;
    if (i >= C_*C_) return;
    int c = i / C_, cp = i % C_;
    const float* ws[4] = {w1, w2, w3, w4};
    #pragma unroll
    for (int k=0;k<4;k++)
        g_wt_h[(size_t)k*C_*C_ + (size_t)cp*C_ + c] = __float2half_rn(16.0f*ws[k][i]);
}
__global__ void p_zeroG2(){
    int i = blockIdx.x*256 + threadIdx.x;
    int nz = MP_ - 514;
    int tot = NLAT_*C_*nz;
    if (i >= tot) return;
    int k  = i % nz;
    int jf = i / nz;
    g_G_h[(size_t)jf*MP_ + 514 + k] = __float2half_rn(0.f);
}

// ---------------- pipelined mma.sync fp16 GEMM, 128x64 tile ----------------
// 8 warps: wm = warp&3 (32 rows), wn = warp>>2 (32 cols). acc 32/thread.
// Stage 12KB: A[0,8K) B[8K,12K); rows 64B wide; 3-stage cp.async; 3 CTAs/SM.
#define STGB 12288
#define NSTG 3
#define SMEM_DYN (NSTG*STGB)

template<int ACT, int DONORM>
__global__ __launch_bounds__(256, 3) void mmagemm(
    const __half* __restrict__ Ah,
    const __half* __restrict__ Bh,
    const __half* __restrict__ Ah2,
    const __half* __restrict__ Bh2, __half* __restrict__ Oh2,
    int zsplit,
    float* __restrict__ Dout,
    __half* __restrict__ Oh,
    const float* __restrict__ biasJ, const float* __restrict__ bscale,
    const float* __restrict__ addsrc,
    int Mrows, int Ncols, int K,
    long sAi, long sAb, long sBi, long sBb,
    long sCi, long sCj, long sCb)
{
    extern __shared__ char dsm[];
    const unsigned sb = smem_u32(dsm);

    const int t    = threadIdx.x;
    const int lane = t & 31;
    const int warp = t >> 5;
    const int g    = lane >> 2;
    const int tig  = lane & 3;
    const int mm   = lane >> 3;
    const int rrl  = lane & 7;
    const int wm   = warp & 3;      // 0..3, 32 rows
    const int wn   = warp >> 2;     // 0..1, 32 cols
    int bz = blockIdx.z;
    if (bz >= zsplit){
        bz -= zsplit;
        if (Ah2){ Ah = Ah2; }
        if (Bh2){ Bh = Bh2; }
        if (Oh2){ Oh = Oh2; }
    }
    const long i0  = (long)blockIdx.y * 128;
    const long j0  = (long)blockIdx.x * 64;

    const __half* Ahb = Ah + (long)bz*sAb;
    const __half* Bhb = Bh + (long)bz*sBb;

    // load mapping: A row = t>>1 (2 chunks each); B row = t>>2 (1 chunk each)
    const int rA_ld  = t >> 1;
    const int rB_ld  = t >> 2;
    const int cB_ld  = t & 3;
    const long aoff  = (i0 + rA_ld) * sAi;
    const long brow  = j0 + rB_ld;
    const bool bok   = brow < (long)Ncols;
    const long boff  = brow * sBi;
    const unsigned soA0 = (unsigned)(rA_ld*64);
    const int swA = (rA_ld>>1)&3;
    const unsigned soB = (unsigned)(8192 + rB_ld*64 + ((cB_ld ^ ((rB_ld>>1)&3)) << 4));
    const long keB0 = (long)cB_ld*8;

    float acc[32];
    #pragma unroll
    for (int i=0;i<32;i++) acc[i] = 0.f;

    auto load_stage = [&](int ks, int s){
        unsigned st = sb + s*STGB;
        long kg = (long)ks*32;
        #pragma unroll
        for (int q=0;q<2;q++){
            int c = (t&1)*2 + q;
            cpa16(st + soA0 + ((c ^ swA) << 4), Ahb + aoff + kg + c*8, true);
        }
        cpa16(st + soB, Bhb + boff + kg + keB0, bok);
    };

    const int nk = K >> 5;
    load_stage(0, 0);
    CP_COMMIT();
    if (nk > 1){ load_stage(1, 1); }
    CP_COMMIT();

    for (int ks = 0; ks < nk; ks++){
        if (ks + 1 < nk) asm volatile("cp.async.wait_group 1;");
        else             asm volatile("cp.async.wait_group 0;");
        __syncthreads();

        const unsigned sA = sb + (ks % NSTG)*STGB;
        const unsigned sB = sA + 8192;
        #pragma unroll
        for (int kk=0; kk<2; kk++){
            unsigned ah[2][4], bh[4][2];
            #pragma unroll
            for (int p=0;p<2;p++){
                int rowB = wn*32 + (p*2 + (mm>>1))*8 + rrl;
                int wB   = kk*8 + (mm&1)*4;
                unsigned ad = sB + (unsigned)swadr(rowB, wB);
                LDMX4(bh[p*2][0], bh[p*2][1], bh[p*2+1][0], bh[p*2+1][1], ad);
            }
            #pragma unroll
            for (int mt=0; mt<2; mt++){
                int rowA = wm*32 + mt*16 + (mm&1)*8 + rrl;
                int wA   = kk*8 + (mm>>1)*4;
                unsigned ad = sA + (unsigned)swadr(rowA, wA);
                LDMX4(ah[mt][0], ah[mt][1], ah[mt][2], ah[mt][3], ad);
            }
            #pragma unroll
            for (int mt=0; mt<2; mt++)
                #pragma unroll
                for (int nt=0; nt<4; nt++) MMA_OP((&acc[(mt*4+nt)*4]), ah[mt], bh[nt]);
        }
        if (ks + 2 < nk){
            load_stage(ks+2, (ks+2) % NSTG);
        }
        CP_COMMIT();
    }

    // ---------------- epilogue ----------------
    float scl = bscale ? bscale[bz] : 1.0f;
    float csum[DONORM ? 8 : 1], csq[DONORM ? 8 : 1];
    if (DONORM){
        #pragma unroll
        for (int i=0;i<8;i++){ csum[i]=0.f; csq[i]=0.f; }
    }

    #pragma unroll
    for (int mt=0; mt<2; mt++){
        long rA = i0 + wm*32 + mt*16 + g;
        #pragma unroll
        for (int nt=0; nt<4; nt++){
            long cB = j0 + wn*32 + nt*8 + 2*tig;
            float* a = &acc[(mt*4+nt)*4];
            #pragma unroll
            for (int h2=0; h2<2; h2++){
                long rowg = rA + h2*8;
                if (rowg >= (long)Mrows) continue;
                long offr = (long)bz*sCb + rowg*sCi;
                if (sCj == 1 && cB + 1 < (long)Ncols){
                    float v0 = a[h2*2+0] * scl;
                    float v1 = a[h2*2+1] * scl;
                    if (biasJ){ v0 += biasJ[cB]; v1 += biasJ[cB+1]; }
                    if (ACT == 1){ v0 = gelu_f(v0); v1 = gelu_f(v1); }
                    long off = offr + cB;
                    if (addsrc){ v0 += addsrc[off]; v1 += addsrc[off+1]; }
                    if (Dout) *(float2*)(Dout + off) = make_float2(v0, v1);
                    if (Oh)   *(__half2*)(Oh + off) = __floats2half2_rn(v0, v1);
                    if (DONORM){
                        csum[nt*2]   += v0; csq[nt*2]   += v0*v0;
                        csum[nt*2+1] += v1; csq[nt*2+1] += v1*v1;
                    }
                } else {
                    #pragma unroll
                    for (int q=0; q<2; q++){
                        long col = cB + q;
                        if (col >= (long)Ncols) continue;
                        float v = a[h2*2+q] * scl;
                        if (biasJ) v += biasJ[col];
                        if (ACT == 1) v = gelu_f(v);
                        long off = offr + col*sCj;
                        if (addsrc) v += addsrc[off];
                        if (Dout) Dout[off] = v;
                        if (Oh)   Oh[off] = __float2half_rn(v);
                    }
                }
            }
        }
    }

    if (DONORM){
        float* ssum = (float*)dsm;
        float* ssq  = ssum + 64;
        __syncthreads();
        if (t < 64){ ssum[t] = 0.f; ssq[t] = 0.f; }
        __syncthreads();
        #pragma unroll
        for (int i=0;i<8;i++){
            int cl = wn*32 + (i>>1)*8 + 2*tig + (i&1);
            atomicAdd(&ssum[cl], csum[i]);
            atomicAdd(&ssq[cl],  csq[i]);
        }
        __syncthreads();
        if (t < 64){
            g_part[0][blockIdx.y][j0 + t] = ssum[t];
            g_part[1][blockIdx.y][j0 + t] = ssq[t];
        }
    }
}

// ---------------- norm + finalize ----------------
__global__ void norm2_k(){
    int c = threadIdx.x;
    float s=0.f, q=0.f;
    for (int b=0;b<1024;b++){ s += g_part[0][b][c]; q += g_part[1][b][c]; }
    float mu = s * (1.0f/(float)S_);
    float var = q * (1.0f/(float)S_) - mu*mu;
    g_mu[c] = mu;
    g_rstd[c] = rsqrtf(var + 1e-3f);
}
__global__ void fin_k(const float* __restrict__ x,
                      const float* __restrict__ gamma,
                      const float* __restrict__ beta,
                      float* __restrict__ out){
    __shared__ float sm[32][33];
    int j  = blockIdx.y;
    int tc = blockIdx.x & 7;
    int tn = blockIdx.x >> 3;
    int tx = threadIdx.x, ty = threadIdx.y;
    #pragma unroll
    for (int k=0;k<4;k++){
        int n = tn*32 + ty + k*8;
        sm[ty+k*8][tx] = g_grids[((size_t)n*NLAT_ + j)*C_ + tc*32 + tx];
    }
    __syncthreads();
    #pragma unroll
    for (int k=0;k<4;k++){
        int c = tc*32 + ty + k*8;
        int n = tn*32 + tx;
        size_t off = (size_t)c*S_ + (size_t)j*NLON_ + n;
        float v = sm[tx][ty+k*8];
        out[off] = (v - g_mu[c])*g_rstd[c]*gamma[c] + beta[c] + x[off];
    }
}

// ---------------- host side ----------------
#define DEVPTR(T, var, sym) T* var; cudaGetSymbolAddress((void**)&var, sym)

static void launch_gemm(int act, int donorm, dim3 grid,
    const __half* Ah, const __half* Bh,
    const __half* Ah2, const __half* Bh2, __half* Oh2, int zsplit,
    float* Dout, __half* Oh,
    const float* biasJ, const float* bscale, const float* addsrc,
    int M, int N, int K,
    long sAi, long sAb, long sBi, long sBb, long sCi, long sCj, long sCb)
{
    if (donorm)
        mmagemm<1,1><<<grid,256,SMEM_DYN>>>(Ah,Bh,Ah2,Bh2,Oh2,zsplit,
            Dout,Oh,biasJ,bscale,addsrc,M,N,K,sAi,sAb,sBi,sBb,sCi,sCj,sCb);
    else if (act)
        mmagemm<1,0><<<grid,256,SMEM_DYN>>>(Ah,Bh,Ah2,Bh2,Oh2,zsplit,
            Dout,Oh,biasJ,bscale,addsrc,M,N,K,sAi,sAb,sBi,sBb,sCi,sCj,sCb);
    else
        mmagemm<0,0><<<grid,256,SMEM_DYN>>>(Ah,Bh,Ah2,Bh2,Oh2,zsplit,
            Dout,Oh,biasJ,bscale,addsrc,M,N,K,sAi,sAb,sBi,sBb,sCi,sCj,sCb);
}

extern "C" void kernel_launch(void* const* d_in, const int* in_sizes, int n_in,
                              void* d_out, int out_size){
    const float* x      = (const float*)d_in[0];
    const float* leg    = (const float*)d_in[1];
    const float* wquad  = (const float*)d_in[2];
    const float* w_real = (const float*)d_in[3];
    const float* w_imag = (const float*)d_in[4];
    const float* m1w1   = (const float*)d_in[5];
    const float* m1b1   = (const float*)d_in[6];
    const float* m1w2   = (const float*)d_in[7];
    const float* m1b2   = (const float*)d_in[8];
    const float* m2w1   = (const float*)d_in[9];
    const float* m2b1   = (const float*)d_in[10];
    const float* m2w2   = (const float*)d_in[11];
    const float* m2b2   = (const float*)d_in[12];
    const float* gamma  = (const float*)d_in[13];
    const float* beta   = (const float*)d_in[14];
    float* out = (float*)d_out;

    cudaFuncSetAttribute(mmagemm<0,0>, cudaFuncAttributeMaxDynamicSharedMemorySize, SMEM_DYN);
    cudaFuncSetAttribute(mmagemm<1,0>, cudaFuncAttributeMaxDynamicSharedMemorySize, SMEM_DYN);
    cudaFuncSetAttribute(mmagemm<1,1>, cudaFuncAttributeMaxDynamicSharedMemorySize, SMEM_DYN);

    DEVPTR(__half, xh, g_x_h);
    DEVPTR(__half, xth,g_xt_h);
    DEVPTR(__half, lwh,g_lw_h);
    DEVPTR(__half, lgh,g_lg_h);
    DEVPTR(__half, wrh,g_wr_h);
    DEVPTR(__half, wih,g_wi_h);
    DEVPTR(__half, Fh, g_F_h);
    DEVPTR(__half, Hh, g_H_h);
    DEVPTR(__half, xrh,g_xr_h);
    DEVPTR(__half, xih,g_xi_h);
    DEVPTR(__half, Gh, g_G_h);
    DEVPTR(__half, mAh,g_mA_h);
    DEVPTR(__half, mBh,g_mB_h);
    DEVPTR(__half, dch,g_dc_h);
    DEVPTR(__half, d2h,g_d2_h);
    DEVPTR(__half, wth,g_wt_h);
    DEVPTR(float, grids, g_grids);
    DEVPTR(float, lsc16, g_lsc16);
    DEVPTR(float, cscale, g_cscale);

    const int BIGZ = 1 << 30;

    // ---- prep ----
    p_dft <<<(unsigned)((D2_SZ+255)/256), 256>>>();
    p_xT2 <<<dim3(128, NLAT_), dim3(32,8)>>>(x);

    // ---- S1: rfft DFT-GEMM, N=256 -> F (ri,m,c,j) ----
    launch_gemm(0, 0, dim3(4, 512, 2),
        xh, dch, nullptr, nullptr, nullptr, BIGZ,
        nullptr, Fh, nullptr, nullptr, nullptr,
        C_*NLAT_, 256, NLON_,
        NLON_, 0, NLON_, (long)M_*NLON_,
        1, (long)C_*NLAT_, (long)M_*C_*NLAT_);
    p_nyq <<<8192, 256>>>();

    p_lw     <<<(unsigned)((LW_SZ/4+255)/256), 256>>>(leg, wquad);
    p_legT   <<<dim3(64, M_), dim3(32,8)>>>(leg);
    p_W2     <<<dim3(16, 256), 256>>>(w_real, w_imag);
    p_wT     <<<(C_*C_+255)/256, 256>>>(m1w1, m1w2, m2w1, m2w2);
    p_zeroG2 <<<(unsigned)((NLAT_*C_*(MP_-514)+255)/256), 256>>>();

    // ---- S2 merged (batch 2M): A=16*lw; B/out switch at zsplit=M ----
    launch_gemm(0, 0, dim3(4, 2, 2*M_),
        lwh, Fh,
        nullptr, Fh + M_*(size_t)C_*NLAT_, Hh + C_, M_,
        nullptr, Hh, nullptr, nullptr, nullptr,
        L_, C_, NLAT_,
        (long)M_*NLAT_, NLAT_, NLAT_, (long)C_*NLAT_,
        (long)M_*K2C_, 1, K2C_);

    // ---- S3 merged (batch 2L), N=256; A/out switch at zsplit=L ----
    launch_gemm(0, 0, dim3(4, 2, 2*L_),
        wrh, Hh,
        wih, nullptr, xih, L_,
        nullptr, xrh, nullptr, lsc16, nullptr,
        C_, 256, K2C_,
        K2C_, (long)C_*K2C_, K2C_, (long)M_*K2C_,
        L_, (long)C_*L_, 1);
    p_s3col <<<2*L_, 256>>>();

    // ---- S4 merged (batch 2M): A=16*lgT; B/out switch at zsplit=M ----
    launch_gemm(0, 0, dim3(4, 2, 2*M_),
        lgh, xrh,
        nullptr, xih, Gh + M_, M_,
        nullptr, Gh, nullptr, nullptr, nullptr,
        NLAT_, C_, L_,
        L_, (long)NLAT_*L_, L_, (long)C_*L_,
        (long)C_*MP_, MP_, 1);

    // ---- S5: irfft + GELU -> fp32 grids (n,j,f) ----
    launch_gemm(1, 0, dim3(1024, 4, 1),
        d2h, Gh, nullptr, nullptr, nullptr, BIGZ,
        grids, nullptr, nullptr, cscale+1, nullptr,
        NLON_, NLAT_*C_, MP_,
        MP_, 0, MP_, 0,
        (long)NLAT_*C_, 1, 0);

    // ---- MLPs (single-pass): B = 16*wT, bscale = 1/16 ----
    launch_gemm(1, 0, dim3(4, 1024, 1),
        xth, wth + 0, nullptr, nullptr, nullptr, BIGZ,
        nullptr, mAh, m1b1, cscale, nullptr,
        S_, C_, C_, C_, 0, C_, 0, C_, 1, 0);
    launch_gemm(1, 0, dim3(4, 1024, 1),
        mAh, wth + C_*C_, nullptr, nullptr, nullptr, BIGZ,
        nullptr, mBh, m1b2, cscale, grids,
        S_, C_, C_, C_, 0, C_, 0, C_, 1, 0);
    launch_gemm(1, 0, dim3(4, 1024, 1),
        mBh, wth + 2*C_*C_, nullptr, nullptr, nullptr, BIGZ,
        nullptr, mAh, m2b1, cscale, nullptr,
        S_, C_, C_, C_, 0, C_, 0, C_, 1, 0);
    launch_gemm(1, 1, dim3(4, 1024, 1),
        mAh, wth + 3*C_*C_, nullptr, nullptr, nullptr, BIGZ,
        grids, nullptr, m2b2, cscale, nullptr,
        S_, C_, C_, C_, 0, C_, 0, C_, 1, 0);

    // ---- instance norm + residual + transpose out ----
    norm2_k<<<1, 256>>>();
    fin_k<<<dim3(128, NLAT_), dim3(32,8)>>>(x, gamma, beta, out);
}

// round 16
// speedup vs baseline: 1.0709x; 1.0035x over previous
#include <cuda_runtime.h>
#include <cuda_fp16.h>
#include <math.h>

#define C_    256
#define NLAT_ 256
#define NLON_ 512
#define L_    256
#define M_    257
#define NREF_ 64
#define S_    (NLAT_*NLON_)
#define K2C_  512
#define MP_   544               // 2*M=514 padded to mult of 32

#define XS_SZ   ((size_t)C_*S_)
#define LW_SZ   ((size_t)L_*M_*NLAT_)
#define LGT_SZ  ((size_t)M_*NLAT_*L_)
#define WC_SZ   ((size_t)L_*C_*K2C_)
#define F_SZ    ((size_t)2*M_*C_*NLAT_)
#define H_SZ    ((size_t)L_*M_*K2C_)
#define XSP_SZ  ((size_t)M_*C_*L_)
#define G2_SZ   ((size_t)NLAT_*C_*MP_)
#define DCS_SZ  ((size_t)2*M_*NLON_)
#define D2_SZ   ((size_t)NLON_*MP_)

__device__ __align__(128) __half g_x_h[XS_SZ];
__device__ __align__(128) __half g_xt_h[XS_SZ];
__device__ __align__(128) __half g_lw_h[LW_SZ];
__device__ __align__(128) __half g_lg_h[LGT_SZ];
__device__ __align__(128) __half g_wr_h[WC_SZ];
__device__ __align__(128) __half g_wi_h[WC_SZ];
__device__ __align__(128) __half g_F_h[F_SZ];
__device__ __align__(128) __half g_H_h[H_SZ];
__device__ __align__(128) __half g_xr_h[XSP_SZ];
__device__ __align__(128) __half g_xi_h[XSP_SZ];
__device__ __align__(128) __half g_G_h[G2_SZ];
__device__ __align__(128) __half g_mA_h[XS_SZ];
__device__ __align__(128) __half g_mB_h[XS_SZ];
__device__ __align__(128) __half g_gh[XS_SZ];     // S5 gelu output (n,j,f) fp16
__device__ __align__(128) __half g_dc_h[DCS_SZ];
__device__ __align__(128) __half g_d2_h[D2_SZ];
__device__ __align__(128) __half g_wt_h[4*C_*C_];
__device__ __align__(128) float g_grids[XS_SZ];
__device__ float g_lsc16[L_];
__device__ float g_cscale[2];        // {1/16, 1/4096}
__device__ float g_part[2][1024][C_];
__device__ float g_mu[C_], g_rstd[C_];

__device__ __forceinline__ float gelu_f(float v){
    return 0.5f*v*(1.0f + erff(v*0.7071067811865476f));
}
__device__ __forceinline__ unsigned smem_u32(const void* p){
    unsigned a;
    asm("{ .reg .u64 t; cvta.to.shared.u64 t, %1; cvt.u32.u64 %0, t; }" : "=r"(a) : "l"(p));
    return a;
}
__device__ __forceinline__ int swadr(int r, int w){
    return r*64 + ((((w>>2) ^ ((r>>1)&3))) << 4) + ((w & 3) << 2);
}
__device__ __forceinline__ void cpa16(unsigned saddr, const void* g, bool v){
    asm volatile("cp.async.cg.shared.global [%0], [%1], 16, %2;"
                 :: "r"(saddr), "l"(g), "r"(v ? 16 : 0));
}
#define CP_COMMIT() asm volatile("cp.async.commit_group;")
#define LDMX4(r0,r1,r2,r3,addr) \
    asm volatile("ldmatrix.sync.aligned.m8n8.x4.shared.b16 {%0,%1,%2,%3}, [%4];" \
        : "=r"(r0),"=r"(r1),"=r"(r2),"=r"(r3) : "r"(addr))
#define MMA_OP(cc, aa, bb) asm volatile( \
    "mma.sync.aligned.m16n8k16.row.col.f32.f16.f16.f32 " \
    "{%0,%1,%2,%3},{%4,%5,%6,%7},{%8,%9},{%0,%1,%2,%3};" \
    : "+f"(cc[0]),"+f"(cc[1]),"+f"(cc[2]),"+f"(cc[3]) \
    : "r"(aa[0]),"r"(aa[1]),"r"(aa[2]),"r"(aa[3]),"r"(bb[0]),"r"(bb[1]))

// ---------------- prep kernels ----------------
__global__ void p_xT2(const float* __restrict__ x){
    __shared__ float sm[32][33];
    int j  = blockIdx.y;
    int tc = blockIdx.x & 7;
    int tn = blockIdx.x >> 3;
    int tx = threadIdx.x, ty = threadIdx.y;
    #pragma unroll
    for (int k=0;k<4;k++){
        int c = tc*32 + ty + k*8;
        size_t offx = (size_t)c*S_ + (size_t)j*NLON_ + tn*32 + tx;
        float v = x[offx];
        sm[ty+k*8][tx] = v;
        g_x_h[offx] = __float2half_rn(v);
    }
    __syncthreads();
    #pragma unroll
    for (int k=0;k<4;k++){
        int n = tn*32 + ty + k*8;
        int c = tc*32 + tx;
        size_t off = ((size_t)n*NLAT_ + j)*C_ + c;
        g_xt_h[off] = __float2half_rn(sm[tx][ty+k*8]);
    }
}
__global__ void p_nyq(){
    int gw   = blockIdx.x*8 + (threadIdx.x >> 5);
    int lane = threadIdx.x & 31;
    const __half2* xr = (const __half2*)(g_x_h + (size_t)gw*NLON_);
    float s = 0.f;
    #pragma unroll 4
    for (int k = lane; k < 256; k += 32){
        float2 v = __half22float2(xr[k]);
        s += v.x - v.y;
    }
    #pragma unroll
    for (int o=16;o>0;o>>=1) s += __shfl_xor_sync(0xffffffffu, s, o);
    if (lane == 0){
        g_F_h[(size_t)256*C_*NLAT_ + gw] = __float2half_rn(s);
        g_F_h[(size_t)M_*C_*NLAT_ + (size_t)256*C_*NLAT_ + gw] = __float2half_rn(0.f);
    }
}
__global__ void p_lw(const float* __restrict__ leg, const float* __restrict__ wq){
    size_t i4 = ((size_t)blockIdx.x*256 + threadIdx.x)*4;
    if (i4 >= LW_SZ) return;
    float4 v = *(const float4*)(leg + i4);
    int w0 = (int)(i4 & (NLAT_-1));
    float a = 16.f*v.x*wq[w0],   b = 16.f*v.y*wq[w0+1];
    float c = 16.f*v.z*wq[w0+2], d = 16.f*v.w*wq[w0+3];
    __half2* o = (__half2*)(g_lw_h + i4);
    o[0] = __floats2half2_rn(a, b);
    o[1] = __floats2half2_rn(c, d);
}
__global__ void p_legT(const float* __restrict__ leg){
    __shared__ float sm[32][33];
    int m  = blockIdx.y;
    int tl = blockIdx.x & 7;
    int tj = blockIdx.x >> 3;
    int tx = threadIdx.x, ty = threadIdx.y;
    #pragma unroll
    for (int k=0;k<4;k++){
        int l = tl*32 + ty + k*8;
        sm[ty+k*8][tx] = leg[(size_t)l*M_*NLAT_ + (size_t)m*NLAT_ + tj*32 + tx];
    }
    __syncthreads();
    #pragma unroll
    for (int k=0;k<4;k++){
        int j = tj*32 + ty + k*8;
        int l = tl*32 + tx;
        size_t off = ((size_t)m*NLAT_ + j)*L_ + l;
        g_lg_h[off] = __float2half_rn(16.0f*sm[tx][ty+k*8]);
    }
}
__global__ void p_W2(const float* __restrict__ wr, const float* __restrict__ wi){
    __shared__ float sr[256][8], si[256][8];
    int f  = blockIdx.y;
    int l0 = blockIdx.x * 16;
    int c  = threadIdx.x;
    int i0min = (l0*(NREF_-1)) / (L_-1);
    if (i0min > NREF_-8) i0min = NREF_-8;
    size_t rb = ((size_t)f*C_ + c)*NREF_ + i0min;
    #pragma unroll
    for (int k=0;k<8;k++){ sr[c][k] = wr[rb+k]; si[c][k] = wi[rb+k]; }
    __syncthreads();
    #pragma unroll 4
    for (int li=0; li<16; li++){
        int l = l0 + li;
        float pos = (float)(l*(NREF_-1)) / (float)(L_-1);
        int i0 = (int)floorf(pos);
        if (i0 > NREF_-2) i0 = NREF_-2;
        float fr = pos - (float)i0;
        int k = i0 - i0min;
        float vre = sr[c][k]*(1.0f-fr) + sr[c][k+1]*fr;
        float vim = si[c][k]*(1.0f-fr) + si[c][k+1]*fr;
        size_t ob = ((size_t)l*C_ + f)*K2C_;
        g_wr_h[ob + c]      = __float2half_rn( vre);
        g_wr_h[ob + C_ + c] = __float2half_rn(-vim);
        g_wi_h[ob + c]      = __float2half_rn( vim);
        g_wi_h[ob + C_ + c] = __float2half_rn( vre);
    }
}
__global__ void p_s3col(){
    int bz = blockIdx.x;
    int l  = bz & (L_-1);
    bool im = bz >= L_;
    const __half* A = (im ? g_wi_h : g_wr_h) + (size_t)l*C_*K2C_;
    __half* O = (im ? g_xi_h : g_xr_h) + (size_t)256*C_*L_ + l;
    __shared__ __half2 sh[256];
    const __half2* Hrow = (const __half2*)(g_H_h + (size_t)l*M_*K2C_ + (size_t)256*K2C_);
    sh[threadIdx.x] = Hrow[threadIdx.x];
    __syncthreads();
    int f = threadIdx.x;
    const __half2* Ar = (const __half2*)(A + (size_t)f*K2C_);
    float s = 0.f;
    #pragma unroll 8
    for (int c2=0; c2<256; c2++){
        float2 a = __half22float2(Ar[c2]);
        float2 h = __half22float2(sh[c2]);
        s += a.x*h.x + a.y*h.y;
    }
    O[(size_t)f*L_] = __float2half_rn(s * g_lsc16[l]);
}
__global__ void p_dft(){
    int i = blockIdx.x*256 + threadIdx.x;
    if (i < L_) g_lsc16[i] = sqrtf(1.0f + (float)i) * (1.0f/(float)C_) * (1.0f/16.0f);
    if (i < 2)  g_cscale[i] = (i==0) ? 0.0625f : (1.0f/4096.0f);
    if (i < (int)DCS_SZ){
        int n = i & 511;
        int m = (i >> 9) % M_;
        int ri = i / (M_*NLON_);
        int a = (m*n) & 511;
        float ang = (float)a * (1.0f/256.0f);
        float v = ri ? -sinpif(ang) : cospif(ang);
        g_dc_h[i] = __float2half_rn(v);
    }
    if (i < (int)D2_SZ){
        int mp = i % MP_;
        int n  = i / MP_;
        float v = 0.f;
        if (mp < M_){
            float wm = (mp==0 || mp==M_-1) ? 1.0f : 2.0f;
            int a = (mp*n) & 511;
            v = wm * cospif((float)a*(1.0f/256.0f)) * 0.5f;
        } else if (mp < 2*M_){
            int m2 = mp - M_;
            float wm = (m2==0 || m2==M_-1) ? 1.0f : 2.0f;
            int a = (m2*n) & 511;
            v = -wm * sinpif((float)a*(1.0f/256.0f)) * 0.5f;
        }
        g_d2_h[i] = __float2half_rn(v);
    }
}
__global__ void p_wT(const float* w1, const float* w2, const float* w3, const float* w4){
    int i = blockIdx.x*256 + threadIdx.x;
    if (i >= C_*C_) return;
    int c = i / C_, cp = i % C_;
    const float* ws[4] = {w1, w2, w3, w4};
    #pragma unroll
    for (int k=0;k<4;k++)
        g_wt_h[(size_t)k*C_*C_ + (size_t)cp*C_ + c] = __float2half_rn(16.0f*ws[k][i]);
}
__global__ void p_zeroG2(){
    int i = blockIdx.x*256 + threadIdx.x;
    int nz = MP_ - 514;
    int tot = NLAT_*C_*nz;
    if (i >= tot) return;
    int k  = i % nz;
    int jf = i / nz;
    g_G_h[(size_t)jf*MP_ + 514 + k] = __float2half_rn(0.f);
}

// ---------------- pipelined mma.sync fp16 GEMM, 128x64 tile ----------------
// 8 warps: wm = warp&3 (32 rows), wn = warp>>2 (32 cols). acc 32/thread.
// Stage 12KB: A[0,8K) B[8K,12K); 4-stage cp.async; 3 CTAs/SM.
#define STGB 12288
#define NSTG 4
#define SMEM_DYN (NSTG*STGB)

template<int ACT, int DONORM>
__global__ __launch_bounds__(256, 3) void mmagemm(
    const __half* __restrict__ Ah,
    const __half* __restrict__ Bh,
    const __half* __restrict__ Ah2,
    const __half* __restrict__ Bh2, __half* __restrict__ Oh2,
    int zsplit,
    float* __restrict__ Dout,
    __half* __restrict__ Oh,
    const float* __restrict__ biasJ, const float* __restrict__ bscale,
    const void* __restrict__ addsrc, int addhalf,
    int Mrows, int Ncols, int K,
    long sAi, long sAb, long sBi, long sBb,
    long sCi, long sCj, long sCb)
{
    extern __shared__ char dsm[];
    const unsigned sb = smem_u32(dsm);

    const int t    = threadIdx.x;
    const int lane = t & 31;
    const int warp = t >> 5;
    const int g    = lane >> 2;
    const int tig  = lane & 3;
    const int mm   = lane >> 3;
    const int rrl  = lane & 7;
    const int wm   = warp & 3;
    const int wn   = warp >> 2;
    int bz = blockIdx.z;
    if (bz >= zsplit){
        bz -= zsplit;
        if (Ah2){ Ah = Ah2; }
        if (Bh2){ Bh = Bh2; }
        if (Oh2){ Oh = Oh2; }
    }
    const long i0  = (long)blockIdx.y * 128;
    const long j0  = (long)blockIdx.x * 64;

    const __half* Ahb = Ah + (long)bz*sAb;
    const __half* Bhb = Bh + (long)bz*sBb;

    const int rA_ld  = t >> 1;
    const int rB_ld  = t >> 2;
    const int cB_ld  = t & 3;
    const long aoff  = (i0 + rA_ld) * sAi;
    const long brow  = j0 + rB_ld;
    const bool bok   = brow < (long)Ncols;
    const long boff  = brow * sBi;
    const unsigned soA0 = (unsigned)(rA_ld*64);
    const int swA = (rA_ld>>1)&3;
    const unsigned soB = (unsigned)(8192 + rB_ld*64 + ((cB_ld ^ ((rB_ld>>1)&3)) << 4));
    const long keB0 = (long)cB_ld*8;

    float acc[32];
    #pragma unroll
    for (int i=0;i<32;i++) acc[i] = 0.f;

    auto load_stage = [&](int ks, int s){
        unsigned st = sb + s*STGB;
        long kg = (long)ks*32;
        #pragma unroll
        for (int q=0;q<2;q++){
            int c = (t&1)*2 + q;
            cpa16(st + soA0 + ((c ^ swA) << 4), Ahb + aoff + kg + c*8, true);
        }
        cpa16(st + soB, Bhb + boff + kg + keB0, bok);
    };

    const int nk = K >> 5;
    load_stage(0, 0);
    CP_COMMIT();
    if (nk > 1){ load_stage(1, 1); }
    CP_COMMIT();
    if (nk > 2){ load_stage(2, 2); }
    CP_COMMIT();

    for (int ks = 0; ks < nk; ks++){
        int rem = nk - 1 - ks;                    // chunks still outstanding after this one
        if (rem >= 2)      asm volatile("cp.async.wait_group 2;");
        else if (rem == 1) asm volatile("cp.async.wait_group 1;");
        else               asm volatile("cp.async.wait_group 0;");
        __syncthreads();

        const unsigned sA = sb + (ks % NSTG)*STGB;
        const unsigned sB = sA + 8192;
        #pragma unroll
        for (int kk=0; kk<2; kk++){
            unsigned ah[2][4], bh[4][2];
            #pragma unroll
            for (int p=0;p<2;p++){
                int rowB = wn*32 + (p*2 + (mm>>1))*8 + rrl;
                int wB   = kk*8 + (mm&1)*4;
                unsigned ad = sB + (unsigned)swadr(rowB, wB);
                LDMX4(bh[p*2][0], bh[p*2][1], bh[p*2+1][0], bh[p*2+1][1], ad);
            }
            #pragma unroll
            for (int mt=0; mt<2; mt++){
                int rowA = wm*32 + mt*16 + (mm&1)*8 + rrl;
                int wA   = kk*8 + (mm>>1)*4;
                unsigned ad = sA + (unsigned)swadr(rowA, wA);
                LDMX4(ah[mt][0], ah[mt][1], ah[mt][2], ah[mt][3], ad);
            }
            #pragma unroll
            for (int mt=0; mt<2; mt++)
                #pragma unroll
                for (int nt=0; nt<4; nt++) MMA_OP((&acc[(mt*4+nt)*4]), ah[mt], bh[nt]);
        }
        if (ks + 3 < nk){
            load_stage(ks+3, (ks+3) % NSTG);
        }
        CP_COMMIT();
    }

    // ---------------- epilogue ----------------
    float scl = bscale ? bscale[bz] : 1.0f;
    float csum[DONORM ? 8 : 1], csq[DONORM ? 8 : 1];
    if (DONORM){
        #pragma unroll
        for (int i=0;i<8;i++){ csum[i]=0.f; csq[i]=0.f; }
    }

    #pragma unroll
    for (int mt=0; mt<2; mt++){
        long rA = i0 + wm*32 + mt*16 + g;
        #pragma unroll
        for (int nt=0; nt<4; nt++){
            long cB = j0 + wn*32 + nt*8 + 2*tig;
            float* a = &acc[(mt*4+nt)*4];
            #pragma unroll
            for (int h2=0; h2<2; h2++){
                long rowg = rA + h2*8;
                if (rowg >= (long)Mrows) continue;
                long offr = (long)bz*sCb + rowg*sCi;
                if (sCj == 1 && cB + 1 < (long)Ncols){
                    float v0 = a[h2*2+0] * scl;
                    float v1 = a[h2*2+1] * scl;
                    if (biasJ){ v0 += biasJ[cB]; v1 += biasJ[cB+1]; }
                    if (ACT == 1){ v0 = gelu_f(v0); v1 = gelu_f(v1); }
                    long off = offr + cB;
                    if (addsrc){
                        if (addhalf){
                            float2 av = __half22float2(*(const __half2*)((const __half*)addsrc + off));
                            v0 += av.x; v1 += av.y;
                        } else {
                            const float* af = (const float*)addsrc;
                            v0 += af[off]; v1 += af[off+1];
                        }
                    }
                    if (Dout) *(float2*)(Dout + off) = make_float2(v0, v1);
                    if (Oh)   *(__half2*)(Oh + off) = __floats2half2_rn(v0, v1);
                    if (DONORM){
                        csum[nt*2]   += v0; csq[nt*2]   += v0*v0;
                        csum[nt*2+1] += v1; csq[nt*2+1] += v1*v1;
                    }
                } else {
                    #pragma unroll
                    for (int q=0; q<2; q++){
                        long col = cB + q;
                        if (col >= (long)Ncols) continue;
                        float v = a[h2*2+q] * scl;
                        if (biasJ) v += biasJ[col];
                        if (ACT == 1) v = gelu_f(v);
                        long off = offr + col*sCj;
                        if (addsrc){
                            if (addhalf) v += __half2float(((const __half*)addsrc)[off]);
                            else         v += ((const float*)addsrc)[off];
                        }
                        if (Dout) Dout[off] = v;
                        if (Oh)   Oh[off] = __float2half_rn(v);
                    }
                }
            }
        }
    }

    if (DONORM){
        float* ssum = (float*)dsm;
        float* ssq  = ssum + 64;
        __syncthreads();
        if (t < 64){ ssum[t] = 0.f; ssq[t] = 0.f; }
        __syncthreads();
        #pragma unroll
        for (int i=0;i<8;i++){
            int cl = wn*32 + (i>>1)*8 + 2*tig + (i&1);
            atomicAdd(&ssum[cl], csum[i]);
            atomicAdd(&ssq[cl],  csq[i]);
        }
        __syncthreads();
        if (t < 64){
            g_part[0][blockIdx.y][j0 + t] = ssum[t];
            g_part[1][blockIdx.y][j0 + t] = ssq[t];
        }
    }
}

// ---------------- norm + finalize ----------------
__global__ void norm2_k(){
    int c = threadIdx.x;
    float s=0.f, q=0.f;
    for (int b=0;b<1024;b++){ s += g_part[0][b][c]; q += g_part[1][b][c]; }
    float mu = s * (1.0f/(float)S_);
    float var = q * (1.0f/(float)S_) - mu*mu;
    g_mu[c] = mu;
    g_rstd[c] = rsqrtf(var + 1e-3f);
}
__global__ void fin_k(const float* __restrict__ x,
                      const float* __restrict__ gamma,
                      const float* __restrict__ beta,
                      float* __restrict__ out){
    __shared__ float sm[32][33];
    int j  = blockIdx.y;
    int tc = blockIdx.x & 7;
    int tn = blockIdx.x >> 3;
    int tx = threadIdx.x, ty = threadIdx.y;
    #pragma unroll
    for (int k=0;k<4;k++){
        int n = tn*32 + ty + k*8;
        sm[ty+k*8][tx] = g_grids[((size_t)n*NLAT_ + j)*C_ + tc*32 + tx];
    }
    __syncthreads();
    #pragma unroll
    for (int k=0;k<4;k++){
        int c = tc*32 + ty + k*8;
        int n = tn*32 + tx;
        size_t off = (size_t)c*S_ + (size_t)j*NLON_ + n;
        float v = sm[tx][ty+k*8];
        out[off] = (v - g_mu[c])*g_rstd[c]*gamma[c] + beta[c] + x[off];
    }
}

// ---------------- host side ----------------
#define DEVPTR(T, var, sym) T* var; cudaGetSymbolAddress((void**)&var, sym)

static void launch_gemm(int act, int donorm, dim3 grid,
    const __half* Ah, const __half* Bh,
    const __half* Ah2, const __half* Bh2, __half* Oh2, int zsplit,
    float* Dout, __half* Oh,
    const float* biasJ, const float* bscale, const void* addsrc, int addhalf,
    int M, int N, int K,
    long sAi, long sAb, long sBi, long sBb, long sCi, long sCj, long sCb)
{
    if (donorm)
        mmagemm<1,1><<<grid,256,SMEM_DYN>>>(Ah,Bh,Ah2,Bh2,Oh2,zsplit,
            Dout,Oh,biasJ,bscale,addsrc,addhalf,M,N,K,sAi,sAb,sBi,sBb,sCi,sCj,sCb);
    else if (act)
        mmagemm<1,0><<<grid,256,SMEM_DYN>>>(Ah,Bh,Ah2,Bh2,Oh2,zsplit,
            Dout,Oh,biasJ,bscale,addsrc,addhalf,M,N,K,sAi,sAb,sBi,sBb,sCi,sCj,sCb);
    else
        mmagemm<0,0><<<grid,256,SMEM_DYN>>>(Ah,Bh,Ah2,Bh2,Oh2,zsplit,
            Dout,Oh,biasJ,bscale,addsrc,addhalf,M,N,K,sAi,sAb,sBi,sBb,sCi,sCj,sCb);
}

extern "C" void kernel_launch(void* const* d_in, const int* in_sizes, int n_in,
                              void* d_out, int out_size){
    const float* x      = (const float*)d_in[0];
    const float* leg    = (const float*)d_in[1];
    const float* wquad  = (const float*)d_in[2];
    const float* w_real = (const float*)d_in[3];
    const float* w_imag = (const float*)d_in[4];
    const float* m1w1   = (const float*)d_in[5];
    const float* m1b1   = (const float*)d_in[6];
    const float* m1w2   = (const float*)d_in[7];
    const float* m1b2   = (const float*)d_in[8];
    const float* m2w1   = (const float*)d_in[9];
    const float* m2b1   = (const float*)d_in[10];
    const float* m2w2   = (const float*)d_in[11];
    const float* m2b2   = (const float*)d_in[12];
    const float* gamma  = (const float*)d_in[13];
    const float* beta   = (const float*)d_in[14];
    float* out = (float*)d_out;

    cudaFuncSetAttribute(mmagemm<0,0>, cudaFuncAttributeMaxDynamicSharedMemorySize, SMEM_DYN);
    cudaFuncSetAttribute(mmagemm<1,0>, cudaFuncAttributeMaxDynamicSharedMemorySize, SMEM_DYN);
    cudaFuncSetAttribute(mmagemm<1,1>, cudaFuncAttributeMaxDynamicSharedMemorySize, SMEM_DYN);

    DEVPTR(__half, xh, g_x_h);
    DEVPTR(__half, xth,g_xt_h);
    DEVPTR(__half, lwh,g_lw_h);
    DEVPTR(__half, lgh,g_lg_h);
    DEVPTR(__half, wrh,g_wr_h);
    DEVPTR(__half, wih,g_wi_h);
    DEVPTR(__half, Fh, g_F_h);
    DEVPTR(__half, Hh, g_H_h);
    DEVPTR(__half, xrh,g_xr_h);
    DEVPTR(__half, xih,g_xi_h);
    DEVPTR(__half, Gh, g_G_h);
    DEVPTR(__half, mAh,g_mA_h);
    DEVPTR(__half, mBh,g_mB_h);
    DEVPTR(__half, ghh,g_gh);
    DEVPTR(__half, dch,g_dc_h);
    DEVPTR(__half, d2h,g_d2_h);
    DEVPTR(__half, wth,g_wt_h);
    DEVPTR(float, grids, g_grids);
    DEVPTR(float, lsc16, g_lsc16);
    DEVPTR(float, cscale, g_cscale);

    const int BIGZ = 1 << 30;

    // ---- prep ----
    p_dft <<<(unsigned)((D2_SZ+255)/256), 256>>>();
    p_xT2 <<<dim3(128, NLAT_), dim3(32,8)>>>(x);

    // ---- S1: rfft DFT-GEMM, N=256 -> F (ri,m,c,j) ----
    launch_gemm(0, 0, dim3(4, 512, 2),
        xh, dch, nullptr, nullptr, nullptr, BIGZ,
        nullptr, Fh, nullptr, nullptr, nullptr, 0,
        C_*NLAT_, 256, NLON_,
        NLON_, 0, NLON_, (long)M_*NLON_,
        1, (long)C_*NLAT_, (long)M_*C_*NLAT_);
    p_nyq <<<8192, 256>>>();

    p_lw     <<<(unsigned)((LW_SZ/4+255)/256), 256>>>(leg, wquad);
    p_legT   <<<dim3(64, M_), dim3(32,8)>>>(leg);
    p_W2     <<<dim3(16, 256), 256>>>(w_real, w_imag);
    p_wT     <<<(C_*C_+255)/256, 256>>>(m1w1, m1w2, m2w1, m2w2);
    p_zeroG2 <<<(unsigned)((NLAT_*C_*(MP_-514)+255)/256), 256>>>();

    // ---- S2 merged (batch 2M): A=16*lw; B/out switch at zsplit=M ----
    launch_gemm(0, 0, dim3(4, 2, 2*M_),
        lwh, Fh,
        nullptr, Fh + M_*(size_t)C_*NLAT_, Hh + C_, M_,
        nullptr, Hh, nullptr, nullptr, nullptr, 0,
        L_, C_, NLAT_,
        (long)M_*NLAT_, NLAT_, NLAT_, (long)C_*NLAT_,
        (long)M_*K2C_, 1, K2C_);

    // ---- S3 merged (batch 2L), N=256; A/out switch at zsplit=L ----
    launch_gemm(0, 0, dim3(4, 2, 2*L_),
        wrh, Hh,
        wih, nullptr, xih, L_,
        nullptr, xrh, nullptr, lsc16, nullptr, 0,
        C_, 256, K2C_,
        K2C_, (long)C_*K2C_, K2C_, (long)M_*K2C_,
        L_, (long)C_*L_, 1);
    p_s3col <<<2*L_, 256>>>();

    // ---- S4 merged (batch 2M): A=16*lgT; B/out switch at zsplit=M ----
    launch_gemm(0, 0, dim3(4, 2, 2*M_),
        lgh, xrh,
        nullptr, xih, Gh + M_, M_,
        nullptr, Gh, nullptr, nullptr, nullptr, 0,
        NLAT_, C_, L_,
        L_, (long)NLAT_*L_, L_, (long)C_*L_,
        (long)C_*MP_, MP_, 1);

    // ---- S5: irfft + GELU -> fp16 gh (n,j,f) ----
    launch_gemm(1, 0, dim3(1024, 4, 1),
        d2h, Gh, nullptr, nullptr, nullptr, BIGZ,
        nullptr, ghh, nullptr, cscale+1, nullptr, 0,
        NLON_, NLAT_*C_, MP_,
        MP_, 0, MP_, 0,
        (long)NLAT_*C_, 1, 0);

    // ---- MLPs (single-pass): B = 16*wT, bscale = 1/16 ----
    launch_gemm(1, 0, dim3(4, 1024, 1),
        xth, wth + 0, nullptr, nullptr, nullptr, BIGZ,
        nullptr, mAh, m1b1, cscale, nullptr, 0,
        S_, C_, C_, C_, 0, C_, 0, C_, 1, 0);
    launch_gemm(1, 0, dim3(4, 1024, 1),
        mAh, wth + C_*C_, nullptr, nullptr, nullptr, BIGZ,
        nullptr, mBh, m1b2, cscale, ghh, 1,
        S_, C_, C_, C_, 0, C_, 0, C_, 1, 0);
    launch_gemm(1, 0, dim3(4, 1024, 1),
        mBh, wth + 2*C_*C_, nullptr, nullptr, nullptr, BIGZ,
        nullptr, mAh, m2b1, cscale, nullptr, 0,
        S_, C_, C_, C_, 0, C_, 0, C_, 1, 0);
    launch_gemm(1, 1, dim3(4, 1024, 1),
        mAh, wth + 3*C_*C_, nullptr, nullptr, nullptr, BIGZ,
        grids, nullptr, m2b2, cscale, nullptr, 0,
        S_, C_, C_, C_, 0, C_, 0, C_, 1, 0);

    // ---- instance norm + residual + transpose out ----
    norm2_k<<<1, 256>>>();
    fin_k<<<dim3(128, NLAT_), dim3(32,8)>>>(x, gamma, beta, out);
}

// round 17
// speedup vs baseline: 1.0813x; 1.0097x over previous
#include <cuda_runtime.h>
#include <cuda_fp16.h>
#include <math.h>

#define C_    256
#define NLAT_ 256
#define NLON_ 512
#define L_    256
#define M_    257
#define NREF_ 64
#define S_    (NLAT_*NLON_)
#define K2C_  512
#define MP_   544               // 2*M=514 padded to mult of 32

#define XS_SZ   ((size_t)C_*S_)
#define LW_SZ   ((size_t)L_*M_*NLAT_)
#define LGT_SZ  ((size_t)M_*NLAT_*L_)
#define WC_SZ   ((size_t)L_*C_*K2C_)
#define F_SZ    ((size_t)2*M_*C_*NLAT_)
#define H_SZ    ((size_t)L_*M_*K2C_)
#define XSP_SZ  ((size_t)M_*C_*L_)
#define G2_SZ   ((size_t)NLAT_*C_*MP_)
#define DCS_SZ  ((size_t)2*M_*NLON_)
#define D2_SZ   ((size_t)NLON_*MP_)

__device__ __align__(128) __half g_x_h[XS_SZ];
__device__ __align__(128) __half g_xt_h[XS_SZ];
__device__ __align__(128) __half g_lw_h[LW_SZ];
__device__ __align__(128) __half g_lg_h[LGT_SZ];
__device__ __align__(128) __half g_wr_h[WC_SZ];
__device__ __align__(128) __half g_wi_h[WC_SZ];
__device__ __align__(128) __half g_F_h[F_SZ];
__device__ __align__(128) __half g_H_h[H_SZ];
__device__ __align__(128) __half g_xr_h[XSP_SZ];
__device__ __align__(128) __half g_xi_h[XSP_SZ];
__device__ __align__(128) __half g_G_h[G2_SZ];
__device__ __align__(128) __half g_mA_h[XS_SZ];
__device__ __align__(128) __half g_mB_h[XS_SZ];
__device__ __align__(128) __half g_gh[XS_SZ];     // S5 gelu out, then y2 (s,c) fp16
__device__ __align__(128) __half g_dc_h[DCS_SZ];
__device__ __align__(128) __half g_d2_h[D2_SZ];
__device__ __align__(128) __half g_wt_h[4*C_*C_];
__device__ float g_lsc16[L_];
__device__ float g_cscale[2];        // {1/16, 1/4096}
__device__ float g_part[2][1024][C_];
__device__ float g_mu[C_], g_rstd[C_];

__device__ __forceinline__ float gelu_f(float v){
    return 0.5f*v*(1.0f + erff(v*0.7071067811865476f));
}
__device__ __forceinline__ unsigned smem_u32(const void* p){
    unsigned a;
    asm("{ .reg .u64 t; cvta.to.shared.u64 t, %1; cvt.u32.u64 %0, t; }" : "=r"(a) : "l"(p));
    return a;
}
__device__ __forceinline__ int swadr(int r, int w){
    return r*64 + ((((w>>2) ^ ((r>>1)&3))) << 4) + ((w & 3) << 2);
}
__device__ __forceinline__ void cpa16(unsigned saddr, const void* g, bool v){
    asm volatile("cp.async.cg.shared.global [%0], [%1], 16, %2;"
                 :: "r"(saddr), "l"(g), "r"(v ? 16 : 0));
}
#define CP_COMMIT() asm volatile("cp.async.commit_group;")
#define LDMX4(r0,r1,r2,r3,addr) \
    asm volatile("ldmatrix.sync.aligned.m8n8.x4.shared.b16 {%0,%1,%2,%3}, [%4];" \
        : "=r"(r0),"=r"(r1),"=r"(r2),"=r"(r3) : "r"(addr))
#define MMA_OP(cc, aa, bb) asm volatile( \
    "mma.sync.aligned.m16n8k16.row.col.f32.f16.f16.f32 " \
    "{%0,%1,%2,%3},{%4,%5,%6,%7},{%8,%9},{%0,%1,%2,%3};" \
    : "+f"(cc[0]),"+f"(cc[1]),"+f"(cc[2]),"+f"(cc[3]) \
    : "r"(aa[0]),"r"(aa[1]),"r"(aa[2]),"r"(aa[3]),"r"(bb[0]),"r"(bb[1]))

// ---------------- prep kernels ----------------
__global__ void p_xT2(const float* __restrict__ x){
    __shared__ float sm[32][33];
    int j  = blockIdx.y;
    int tc = blockIdx.x & 7;
    int tn = blockIdx.x >> 3;
    int tx = threadIdx.x, ty = threadIdx.y;
    #pragma unroll
    for (int k=0;k<4;k++){
        int c = tc*32 + ty + k*8;
        size_t offx = (size_t)c*S_ + (size_t)j*NLON_ + tn*32 + tx;
        float v = x[offx];
        sm[ty+k*8][tx] = v;
        g_x_h[offx] = __float2half_rn(v);
    }
    __syncthreads();
    #pragma unroll
    for (int k=0;k<4;k++){
        int n = tn*32 + ty + k*8;
        int c = tc*32 + tx;
        size_t off = ((size_t)n*NLAT_ + j)*C_ + c;
        g_xt_h[off] = __float2half_rn(sm[tx][ty+k*8]);
    }
}
__global__ void p_nyq(){
    int gw   = blockIdx.x*8 + (threadIdx.x >> 5);
    int lane = threadIdx.x & 31;
    const __half2* xr = (const __half2*)(g_x_h + (size_t)gw*NLON_);
    float s = 0.f;
    #pragma unroll 4
    for (int k = lane; k < 256; k += 32){
        float2 v = __half22float2(xr[k]);
        s += v.x - v.y;
    }
    #pragma unroll
    for (int o=16;o>0;o>>=1) s += __shfl_xor_sync(0xffffffffu, s, o);
    if (lane == 0){
        g_F_h[(size_t)256*C_*NLAT_ + gw] = __float2half_rn(s);
        g_F_h[(size_t)M_*C_*NLAT_ + (size_t)256*C_*NLAT_ + gw] = __float2half_rn(0.f);
    }
}
__global__ void p_lw(const float* __restrict__ leg, const float* __restrict__ wq){
    size_t i4 = ((size_t)blockIdx.x*256 + threadIdx.x)*4;
    if (i4 >= LW_SZ) return;
    float4 v = *(const float4*)(leg + i4);
    int w0 = (int)(i4 & (NLAT_-1));
    float a = 16.f*v.x*wq[w0],   b = 16.f*v.y*wq[w0+1];
    float c = 16.f*v.z*wq[w0+2], d = 16.f*v.w*wq[w0+3];
    __half2* o = (__half2*)(g_lw_h + i4);
    o[0] = __floats2half2_rn(a, b);
    o[1] = __floats2half2_rn(c, d);
}
__global__ void p_legT(const float* __restrict__ leg){
    __shared__ float sm[32][33];
    int m  = blockIdx.y;
    int tl = blockIdx.x & 7;
    int tj = blockIdx.x >> 3;
    int tx = threadIdx.x, ty = threadIdx.y;
    #pragma unroll
    for (int k=0;k<4;k++){
        int l = tl*32 + ty + k*8;
        sm[ty+k*8][tx] = leg[(size_t)l*M_*NLAT_ + (size_t)m*NLAT_ + tj*32 + tx];
    }
    __syncthreads();
    #pragma unroll
    for (int k=0;k<4;k++){
        int j = tj*32 + ty + k*8;
        int l = tl*32 + tx;
        size_t off = ((size_t)m*NLAT_ + j)*L_ + l;
        g_lg_h[off] = __float2half_rn(16.0f*sm[tx][ty+k*8]);
    }
}
__global__ void p_W2(const float* __restrict__ wr, const float* __restrict__ wi){
    __shared__ float sr[256][8], si[256][8];
    int f  = blockIdx.y;
    int l0 = blockIdx.x * 16;
    int c  = threadIdx.x;
    int i0min = (l0*(NREF_-1)) / (L_-1);
    if (i0min > NREF_-8) i0min = NREF_-8;
    size_t rb = ((size_t)f*C_ + c)*NREF_ + i0min;
    #pragma unroll
    for (int k=0;k<8;k++){ sr[c][k] = wr[rb+k]; si[c][k] = wi[rb+k]; }
    __syncthreads();
    #pragma unroll 4
    for (int li=0; li<16; li++){
        int l = l0 + li;
        float pos = (float)(l*(NREF_-1)) / (float)(L_-1);
        int i0 = (int)floorf(pos);
        if (i0 > NREF_-2) i0 = NREF_-2;
        float fr = pos - (float)i0;
        int k = i0 - i0min;
        float vre = sr[c][k]*(1.0f-fr) + sr[c][k+1]*fr;
        float vim = si[c][k]*(1.0f-fr) + si[c][k+1]*fr;
        size_t ob = ((size_t)l*C_ + f)*K2C_;
        g_wr_h[ob + c]      = __float2half_rn( vre);
        g_wr_h[ob + C_ + c] = __float2half_rn(-vim);
        g_wi_h[ob + c]      = __float2half_rn( vim);
        g_wi_h[ob + C_ + c] = __float2half_rn( vre);
    }
}
__global__ void p_s3col(){
    int bz = blockIdx.x;
    int l  = bz & (L_-1);
    bool im = bz >= L_;
    const __half* A = (im ? g_wi_h : g_wr_h) + (size_t)l*C_*K2C_;
    __half* O = (im ? g_xi_h : g_xr_h) + (size_t)256*C_*L_ + l;
    __shared__ __half2 sh[256];
    const __half2* Hrow = (const __half2*)(g_H_h + (size_t)l*M_*K2C_ + (size_t)256*K2C_);
    sh[threadIdx.x] = Hrow[threadIdx.x];
    __syncthreads();
    int f = threadIdx.x;
    const __half2* Ar = (const __half2*)(A + (size_t)f*K2C_);
    float s = 0.f;
    #pragma unroll 8
    for (int c2=0; c2<256; c2++){
        float2 a = __half22float2(Ar[c2]);
        float2 h = __half22float2(sh[c2]);
        s += a.x*h.x + a.y*h.y;
    }
    O[(size_t)f*L_] = __float2half_rn(s * g_lsc16[l]);
}
__global__ void p_dft(){
    int i = blockIdx.x*256 + threadIdx.x;
    if (i < L_) g_lsc16[i] = sqrtf(1.0f + (float)i) * (1.0f/(float)C_) * (1.0f/16.0f);
    if (i < 2)  g_cscale[i] = (i==0) ? 0.0625f : (1.0f/4096.0f);
    if (i < (int)DCS_SZ){
        int n = i & 511;
        int m = (i >> 9) % M_;
        int ri = i / (M_*NLON_);
        int a = (m*n) & 511;
        float ang = (float)a * (1.0f/256.0f);
        float v = ri ? -sinpif(ang) : cospif(ang);
        g_dc_h[i] = __float2half_rn(v);
    }
    if (i < (int)D2_SZ){
        int mp = i % MP_;
        int n  = i / MP_;
        float v = 0.f;
        if (mp < M_){
            float wm = (mp==0 || mp==M_-1) ? 1.0f : 2.0f;
            int a = (mp*n) & 511;
            v = wm * cospif((float)a*(1.0f/256.0f)) * 0.5f;
        } else if (mp < 2*M_){
            int m2 = mp - M_;
            float wm = (m2==0 || m2==M_-1) ? 1.0f : 2.0f;
            int a = (m2*n) & 511;
            v = -wm * sinpif((float)a*(1.0f/256.0f)) * 0.5f;
        }
        g_d2_h[i] = __float2half_rn(v);
    }
}
__global__ void p_wT(const float* w1, const float* w2, const float* w3, const float* w4){
    int i = blockIdx.x*256 + threadIdx.x;
    if (i >= C_*C_) return;
    int c = i / C_, cp = i % C_;
    const float* ws[4] = {w1, w2, w3, w4};
    #pragma unroll
    for (int k=0;k<4;k++)
        g_wt_h[(size_t)k*C_*C_ + (size_t)cp*C_ + c] = __float2half_rn(16.0f*ws[k][i]);
}
__global__ void p_zeroG2(){
    int i = blockIdx.x*256 + threadIdx.x;
    int nz = MP_ - 514;
    int tot = NLAT_*C_*nz;
    if (i >= tot) return;
    int k  = i % nz;
    int jf = i / nz;
    g_G_h[(size_t)jf*MP_ + 514 + k] = __float2half_rn(0.f);
}

// ---------------- pipelined mma.sync fp16 GEMM, 128x64 tile ----------------
#define STGB 12288
#define NSTG 4
#define SMEM_DYN (NSTG*STGB)

template<int ACT, int DONORM>
__global__ __launch_bounds__(256, 3) void mmagemm(
    const __half* __restrict__ Ah,
    const __half* __restrict__ Bh,
    const __half* __restrict__ Ah2,
    const __half* __restrict__ Bh2, __half* __restrict__ Oh2,
    int zsplit,
    float* __restrict__ Dout,
    __half* __restrict__ Oh,
    const float* __restrict__ biasJ, const float* __restrict__ bscale,
    const void* __restrict__ addsrc, int addhalf,
    int Mrows, int Ncols, int K,
    long sAi, long sAb, long sBi, long sBb,
    long sCi, long sCj, long sCb)
{
    extern __shared__ char dsm[];
    const unsigned sb = smem_u32(dsm);

    const int t    = threadIdx.x;
    const int lane = t & 31;
    const int warp = t >> 5;
    const int g    = lane >> 2;
    const int tig  = lane & 3;
    const int mm   = lane >> 3;
    const int rrl  = lane & 7;
    const int wm   = warp & 3;
    const int wn   = warp >> 2;
    int bz = blockIdx.z;
    if (bz >= zsplit){
        bz -= zsplit;
        if (Ah2){ Ah = Ah2; }
        if (Bh2){ Bh = Bh2; }
        if (Oh2){ Oh = Oh2; }
    }
    const long i0  = (long)blockIdx.y * 128;
    const long j0  = (long)blockIdx.x * 64;

    const __half* Ahb = Ah + (long)bz*sAb;
    const __half* Bhb = Bh + (long)bz*sBb;

    const int rA_ld  = t >> 1;
    const int rB_ld  = t >> 2;
    const int cB_ld  = t & 3;
    const long aoff  = (i0 + rA_ld) * sAi;
    const long brow  = j0 + rB_ld;
    const bool bok   = brow < (long)Ncols;
    const long boff  = brow * sBi;
    const unsigned soA0 = (unsigned)(rA_ld*64);
    const int swA = (rA_ld>>1)&3;
    const unsigned soB = (unsigned)(8192 + rB_ld*64 + ((cB_ld ^ ((rB_ld>>1)&3)) << 4));
    const long keB0 = (long)cB_ld*8;

    float acc[32];
    #pragma unroll
    for (int i=0;i<32;i++) acc[i] = 0.f;

    auto load_stage = [&](int ks, int s){
        unsigned st = sb + s*STGB;
        long kg = (long)ks*32;
        #pragma unroll
        for (int q=0;q<2;q++){
            int c = (t&1)*2 + q;
            cpa16(st + soA0 + ((c ^ swA) << 4), Ahb + aoff + kg + c*8, true);
        }
        cpa16(st + soB, Bhb + boff + kg + keB0, bok);
    };

    const int nk = K >> 5;
    load_stage(0, 0);
    CP_COMMIT();
    if (nk > 1){ load_stage(1, 1); }
    CP_COMMIT();
    if (nk > 2){ load_stage(2, 2); }
    CP_COMMIT();

    for (int ks = 0; ks < nk; ks++){
        int rem = nk - 1 - ks;
        if (rem >= 2)      asm volatile("cp.async.wait_group 2;");
        else if (rem == 1) asm volatile("cp.async.wait_group 1;");
        else               asm volatile("cp.async.wait_group 0;");
        __syncthreads();

        const unsigned sA = sb + (ks % NSTG)*STGB;
        const unsigned sB = sA + 8192;
        #pragma unroll
        for (int kk=0; kk<2; kk++){
            unsigned ah[2][4], bh[4][2];
            #pragma unroll
            for (int p=0;p<2;p++){
                int rowB = wn*32 + (p*2 + (mm>>1))*8 + rrl;
                int wB   = kk*8 + (mm&1)*4;
                unsigned ad = sB + (unsigned)swadr(rowB, wB);
                LDMX4(bh[p*2][0], bh[p*2][1], bh[p*2+1][0], bh[p*2+1][1], ad);
            }
            #pragma unroll
            for (int mt=0; mt<2; mt++){
                int rowA = wm*32 + mt*16 + (mm&1)*8 + rrl;
                int wA   = kk*8 + (mm>>1)*4;
                unsigned ad = sA + (unsigned)swadr(rowA, wA);
                LDMX4(ah[mt][0], ah[mt][1], ah[mt][2], ah[mt][3], ad);
            }
            #pragma unroll
            for (int mt=0; mt<2; mt++)
                #pragma unroll
                for (int nt=0; nt<4; nt++) MMA_OP((&acc[(mt*4+nt)*4]), ah[mt], bh[nt]);
        }
        if (ks + 3 < nk){
            load_stage(ks+3, (ks+3) % NSTG);
        }
        CP_COMMIT();
    }

    // ---------------- epilogue ----------------
    float scl = bscale ? bscale[bz] : 1.0f;
    float csum[DONORM ? 8 : 1], csq[DONORM ? 8 : 1];
    if (DONORM){
        #pragma unroll
        for (int i=0;i<8;i++){ csum[i]=0.f; csq[i]=0.f; }
    }

    #pragma unroll
    for (int mt=0; mt<2; mt++){
        long rA = i0 + wm*32 + mt*16 + g;
        #pragma unroll
        for (int nt=0; nt<4; nt++){
            long cB = j0 + wn*32 + nt*8 + 2*tig;
            float* a = &acc[(mt*4+nt)*4];
            #pragma unroll
            for (int h2=0; h2<2; h2++){
                long rowg = rA + h2*8;
                if (rowg >= (long)Mrows) continue;
                long offr = (long)bz*sCb + rowg*sCi;
                if (sCj == 1 && cB + 1 < (long)Ncols){
                    float v0 = a[h2*2+0] * scl;
                    float v1 = a[h2*2+1] * scl;
                    if (biasJ){ v0 += biasJ[cB]; v1 += biasJ[cB+1]; }
                    if (ACT == 1){ v0 = gelu_f(v0); v1 = gelu_f(v1); }
                    long off = offr + cB;
                    if (addsrc){
                        if (addhalf){
                            float2 av = __half22float2(*(const __half2*)((const __half*)addsrc + off));
                            v0 += av.x; v1 += av.y;
                        } else {
                            const float* af = (const float*)addsrc;
                            v0 += af[off]; v1 += af[off+1];
                        }
                    }
                    if (Dout) *(float2*)(Dout + off) = make_float2(v0, v1);
                    if (Oh)   *(__half2*)(Oh + off) = __floats2half2_rn(v0, v1);
                    if (DONORM){
                        csum[nt*2]   += v0; csq[nt*2]   += v0*v0;
                        csum[nt*2+1] += v1; csq[nt*2+1] += v1*v1;
                    }
                } else {
                    #pragma unroll
                    for (int q=0; q<2; q++){
                        long col = cB + q;
                        if (col >= (long)Ncols) continue;
                        float v = a[h2*2+q] * scl;
                        if (biasJ) v += biasJ[col];
                        if (ACT == 1) v = gelu_f(v);
                        long off = offr + col*sCj;
                        if (addsrc){
                            if (addhalf) v += __half2float(((const __half*)addsrc)[off]);
                            else         v += ((const float*)addsrc)[off];
                        }
                        if (Dout) Dout[off] = v;
                        if (Oh)   Oh[off] = __float2half_rn(v);
                    }
                }
            }
        }
    }

    if (DONORM){
        float* ssum = (float*)dsm;
        float* ssq  = ssum + 64;
        __syncthreads();
        if (t < 64){ ssum[t] = 0.f; ssq[t] = 0.f; }
        __syncthreads();
        #pragma unroll
        for (int i=0;i<8;i++){
            int cl = wn*32 + (i>>1)*8 + 2*tig + (i&1);
            atomicAdd(&ssum[cl], csum[i]);
            atomicAdd(&ssq[cl],  csq[i]);
        }
        __syncthreads();
        if (t < 64){
            g_part[0][blockIdx.y][j0 + t] = ssum[t];
            g_part[1][blockIdx.y][j0 + t] = ssq[t];
        }
    }
}

// ---------------- norm + finalize ----------------
__global__ void norm2_k(){
    int c = threadIdx.x;
    float s=0.f, q=0.f;
    for (int b=0;b<1024;b++){ s += g_part[0][b][c]; q += g_part[1][b][c]; }
    float mu = s * (1.0f/(float)S_);
    float var = q * (1.0f/(float)S_) - mu*mu;
    g_mu[c] = mu;
    g_rstd[c] = rsqrtf(var + 1e-3f);
}
__global__ void fin_k(const float* __restrict__ x,
                      const float* __restrict__ gamma,
                      const float* __restrict__ beta,
                      float* __restrict__ out){
    __shared__ float sm[32][33];
    int j  = blockIdx.y;
    int tc = blockIdx.x & 7;
    int tn = blockIdx.x >> 3;
    int tx = threadIdx.x, ty = threadIdx.y;
    #pragma unroll
    for (int k=0;k<4;k++){
        int n = tn*32 + ty + k*8;
        sm[ty+k*8][tx] = __half2float(g_gh[((size_t)n*NLAT_ + j)*C_ + tc*32 + tx]);
    }
    __syncthreads();
    #pragma unroll
    for (int k=0;k<4;k++){
        int c = tc*32 + ty + k*8;
        int n = tn*32 + tx;
        size_t off = (size_t)c*S_ + (size_t)j*NLON_ + n;
        float v = sm[tx][ty+k*8];
        out[off] = (v - g_mu[c])*g_rstd[c]*gamma[c] + beta[c] + x[off];
    }
}

// ---------------- host side ----------------
#define DEVPTR(T, var, sym) T* var; cudaGetSymbolAddress((void**)&var, sym)

static void launch_gemm(int act, int donorm, dim3 grid,
    const __half* Ah, const __half* Bh,
    const __half* Ah2, const __half* Bh2, __half* Oh2, int zsplit,
    float* Dout, __half* Oh,
    const float* biasJ, const float* bscale, const void* addsrc, int addhalf,
    int M, int N, int K,
    long sAi, long sAb, long sBi, long sBb, long sCi, long sCj, long sCb)
{
    if (donorm)
        mmagemm<1,1><<<grid,256,SMEM_DYN>>>(Ah,Bh,Ah2,Bh2,Oh2,zsplit,
            Dout,Oh,biasJ,bscale,addsrc,addhalf,M,N,K,sAi,sAb,sBi,sBb,sCi,sCj,sCb);
    else if (act)
        mmagemm<1,0><<<grid,256,SMEM_DYN>>>(Ah,Bh,Ah2,Bh2,Oh2,zsplit,
            Dout,Oh,biasJ,bscale,addsrc,addhalf,M,N,K,sAi,sAb,sBi,sBb,sCi,sCj,sCb);
    else
        mmagemm<0,0><<<grid,256,SMEM_DYN>>>(Ah,Bh,Ah2,Bh2,Oh2,zsplit,
            Dout,Oh,biasJ,bscale,addsrc,addhalf,M,N,K,sAi,sAb,sBi,sBb,sCi,sCj,sCb);
}

extern "C" void kernel_launch(void* const* d_in, const int* in_sizes, int n_in,
                              void* d_out, int out_size){
    const float* x      = (const float*)d_in[0];
    const float* leg    = (const float*)d_in[1];
    const float* wquad  = (const float*)d_in[2];
    const float* w_real = (const float*)d_in[3];
    const float* w_imag = (const float*)d_in[4];
    const float* m1w1   = (const float*)d_in[5];
    const float* m1b1   = (const float*)d_in[6];
    const float* m1w2   = (const float*)d_in[7];
    const float* m1b2   = (const float*)d_in[8];
    const float* m2w1   = (const float*)d_in[9];
    const float* m2b1   = (const float*)d_in[10];
    const float* m2w2   = (const float*)d_in[11];
    const float* m2b2   = (const float*)d_in[12];
    const float* gamma  = (const float*)d_in[13];
    const float* beta   = (const float*)d_in[14];
    float* out = (float*)d_out;

    cudaFuncSetAttribute(mmagemm<0,0>, cudaFuncAttributeMaxDynamicSharedMemorySize, SMEM_DYN);
    cudaFuncSetAttribute(mmagemm<1,0>, cudaFuncAttributeMaxDynamicSharedMemorySize, SMEM_DYN);
    cudaFuncSetAttribute(mmagemm<1,1>, cudaFuncAttributeMaxDynamicSharedMemorySize, SMEM_DYN);

    DEVPTR(__half, xh, g_x_h);
    DEVPTR(__half, xth,g_xt_h);
    DEVPTR(__half, lwh,g_lw_h);
    DEVPTR(__half, lgh,g_lg_h);
    DEVPTR(__half, wrh,g_wr_h);
    DEVPTR(__half, wih,g_wi_h);
    DEVPTR(__half, Fh, g_F_h);
    DEVPTR(__half, Hh, g_H_h);
    DEVPTR(__half, xrh,g_xr_h);
    DEVPTR(__half, xih,g_xi_h);
    DEVPTR(__half, Gh, g_G_h);
    DEVPTR(__half, mAh,g_mA_h);
    DEVPTR(__half, mBh,g_mB_h);
    DEVPTR(__half, ghh,g_gh);
    DEVPTR(__half, dch,g_dc_h);
    DEVPTR(__half, d2h,g_d2_h);
    DEVPTR(__half, wth,g_wt_h);
    DEVPTR(float, lsc16, g_lsc16);
    DEVPTR(float, cscale, g_cscale);

    const int BIGZ = 1 << 30;

    // ---- prep ----
    p_dft <<<(unsigned)((D2_SZ+255)/256), 256>>>();
    p_xT2 <<<dim3(128, NLAT_), dim3(32,8)>>>(x);

    // ---- S1: rfft DFT-GEMM, N=256 -> F (ri,m,c,j) ----
    launch_gemm(0, 0, dim3(4, 512, 2),
        xh, dch, nullptr, nullptr, nullptr, BIGZ,
        nullptr, Fh, nullptr, nullptr, nullptr, 0,
        C_*NLAT_, 256, NLON_,
        NLON_, 0, NLON_, (long)M_*NLON_,
        1, (long)C_*NLAT_, (long)M_*C_*NLAT_);
    p_nyq <<<8192, 256>>>();

    p_lw     <<<(unsigned)((LW_SZ/4+255)/256), 256>>>(leg, wquad);
    p_legT   <<<dim3(64, M_), dim3(32,8)>>>(leg);
    p_W2     <<<dim3(16, 256), 256>>>(w_real, w_imag);
    p_wT     <<<(C_*C_+255)/256, 256>>>(m1w1, m1w2, m2w1, m2w2);
    p_zeroG2 <<<(unsigned)((NLAT_*C_*(MP_-514)+255)/256), 256>>>();

    // ---- S2 merged (batch 2M): A=16*lw; B/out switch at zsplit=M ----
    launch_gemm(0, 0, dim3(4, 2, 2*M_),
        lwh, Fh,
        nullptr, Fh + M_*(size_t)C_*NLAT_, Hh + C_, M_,
        nullptr, Hh, nullptr, nullptr, nullptr, 0,
        L_, C_, NLAT_,
        (long)M_*NLAT_, NLAT_, NLAT_, (long)C_*NLAT_,
        (long)M_*K2C_, 1, K2C_);

    // ---- S3 merged (batch 2L), N=256; A/out switch at zsplit=L ----
    launch_gemm(0, 0, dim3(4, 2, 2*L_),
        wrh, Hh,
        wih, nullptr, xih, L_,
        nullptr, xrh, nullptr, lsc16, nullptr, 0,
        C_, 256, K2C_,
        K2C_, (long)C_*K2C_, K2C_, (long)M_*K2C_,
        L_, (long)C_*L_, 1);
    p_s3col <<<2*L_, 256>>>();

    // ---- S4 merged (batch 2M): A=16*lgT; B/out switch at zsplit=M ----
    launch_gemm(0, 0, dim3(4, 2, 2*M_),
        lgh, xrh,
        nullptr, xih, Gh + M_, M_,
        nullptr, Gh, nullptr, nullptr, nullptr, 0,
        NLAT_, C_, L_,
        L_, (long)NLAT_*L_, L_, (long)C_*L_,
        (long)C_*MP_, MP_, 1);

    // ---- S5: irfft + GELU -> fp16 gh (n,j,f) ----
    launch_gemm(1, 0, dim3(1024, 4, 1),
        d2h, Gh, nullptr, nullptr, nullptr, BIGZ,
        nullptr, ghh, nullptr, cscale+1, nullptr, 0,
        NLON_, NLAT_*C_, MP_,
        MP_, 0, MP_, 0,
        (long)NLAT_*C_, 1, 0);

    // ---- MLPs (single-pass): B = 16*wT, bscale = 1/16 ----
    launch_gemm(1, 0, dim3(4, 1024, 1),
        xth, wth + 0, nullptr, nullptr, nullptr, BIGZ,
        nullptr, mAh, m1b1, cscale, nullptr, 0,
        S_, C_, C_, C_, 0, C_, 0, C_, 1, 0);
    launch_gemm(1, 0, dim3(4, 1024, 1),
        mAh, wth + C_*C_, nullptr, nullptr, nullptr, BIGZ,
        nullptr, mBh, m1b2, cscale, ghh, 1,
        S_, C_, C_, C_, 0, C_, 0, C_, 1, 0);
    launch_gemm(1, 0, dim3(4, 1024, 1),
        mBh, wth + 2*C_*C_, nullptr, nullptr, nullptr, BIGZ,
        nullptr, mAh, m2b1, cscale, nullptr, 0,
        S_, C_, C_, C_, 0, C_, 0, C_, 1, 0);
    // MLP4: fused norm sums (fp32) + y2 stored fp16 into gh
    launch_gemm(1, 1, dim3(4, 1024, 1),
        mAh, wth + 3*C_*C_, nullptr, nullptr, nullptr, BIGZ,
        nullptr, ghh, m2b2, cscale, nullptr, 0,
        S_, C_, C_, C_, 0, C_, 0, C_, 1, 0);

    // ---- instance norm + residual + transpose out ----
    norm2_k<<<1, 256>>>();
    fin_k<<<dim3(128, NLAT_), dim3(32,8)>>>(x, gamma, beta, out);
}